// round 10
// baseline (speedup 1.0000x reference)
#include <cuda_runtime.h>
#include <cuda_bf16.h>
#include <math.h>

#define NB 64
#define TT 512
#define DD 1024
#define HH 1024
#define FH 4096   // 4*H
#define MM 32768  // NB*TT

typedef unsigned long long ull;

// Scratch (device globals — no runtime allocation allowed)
__device__ float g_xz[(size_t)TT * NB * FH];              // (t, n, 4H) : 512 MB
__device__ __nv_bfloat16 g_wsplit[(size_t)2048 * FH];     // Wh hi|lo, cols permuted
__device__ __nv_bfloat16 g_wxstack[(size_t)3072 * FH];    // [Wx_hi; Wx_lo; Wx_hi]
__device__ __nv_bfloat16 g_xh[(size_t)MM * DD];           // x hi
__device__ __nv_bfloat16 g_xl[(size_t)MM * DD];           // x lo
__device__ __nv_bfloat16 g_hh[2][NB * HH];                // h hi, double-buffered
__device__ __nv_bfloat16 g_hl[2][NB * HH];                // h lo
// Fine-grained step flags (replace the global barrier)
__device__ unsigned g_ready[TT + 1][4];   // [t][g]: #blocks of group g that published h(t)
__device__ unsigned g_done[TT];           // [t]: #blocks done READING h(t)

// ---- helpers ----------------------------------------------------------------
__device__ __forceinline__ unsigned s2u(const void* p) {
    return (unsigned)__cvta_generic_to_shared(p);
}
__device__ __forceinline__ void cp16(void* s, const void* g) {
    asm volatile("cp.async.cg.shared.global [%0], [%1], 16;" :: "r"(s2u(s)), "l"(g));
}
__device__ __forceinline__ unsigned ld_acquire(const unsigned* p) {
    unsigned v;
    asm volatile("ld.acquire.gpu.u32 %0, [%1];" : "=r"(v) : "l"(p) : "memory");
    return v;
}
__device__ __forceinline__ void red_release_add1(unsigned* p) {
    asm volatile("red.release.gpu.global.add.u32 [%0], %1;" :: "l"(p), "r"(1u) : "memory");
}
__device__ __forceinline__ void spin_until(const unsigned* p, unsigned target) {
    while (ld_acquire(p) < target) {}
}
#define LDSM_X4(r0, r1, r2, r3, addr) \
    asm volatile("ldmatrix.sync.aligned.m8n8.x4.shared.b16 {%0,%1,%2,%3}, [%4];" \
                 : "=r"(r0), "=r"(r1), "=r"(r2), "=r"(r3) : "r"(addr))
#define LDSM_X2T(r0, r1, addr) \
    asm volatile("ldmatrix.sync.aligned.m8n8.x2.trans.shared.b16 {%0,%1}, [%2];" \
                 : "=r"(r0), "=r"(r1) : "r"(addr))
#define LDSM_X4T(r0, r1, r2, r3, addr) \
    asm volatile("ldmatrix.sync.aligned.m8n8.x4.trans.shared.b16 {%0,%1,%2,%3}, [%4];" \
                 : "=r"(r0), "=r"(r1), "=r"(r2), "=r"(r3) : "r"(addr))
#define MMA16816(d0, d1, d2, d3, a0, a1, a2, a3, b0, b1) \
    asm volatile("mma.sync.aligned.m16n8k16.row.col.f32.bf16.bf16.f32 " \
                 "{%0,%1,%2,%3}, {%4,%5,%6,%7}, {%8,%9}, {%0,%1,%2,%3};" \
                 : "+f"(d0), "+f"(d1), "+f"(d2), "+f"(d3) \
                 : "r"(a0), "r"(a1), "r"(a2), "r"(a3), "r"(b0), "r"(b1))

// ---------------------------------------------------------------------------
// Init / precompute kernels
// ---------------------------------------------------------------------------
__global__ void init_kernel(const float* __restrict__ h0) {
    int i = blockIdx.x * blockDim.x + threadIdx.x;
    if (i < (TT + 1) * 4) ((unsigned*)g_ready)[i] = 0;
    if (i < TT) g_done[i] = 0;
    if (i < NB * HH) {
        float v = h0[i];
        __nv_bfloat16 hi = __float2bfloat16(v);
        g_hh[0][i] = hi;
        g_hl[0][i] = __float2bfloat16(v - __bfloat162float(hi));
    }
}

// Wh split + block-column permute: col_new = blk*32 + g*8 + j
__global__ void split_wh_kernel(const float* __restrict__ Wh) {
    int i = blockIdx.x * blockDim.x + threadIdx.x;
    if (i >= DD * FH) return;
    int k = i >> 12;
    int co = i & 4095;
    float w = Wh[i];
    __nv_bfloat16 hi = __float2bfloat16(w);
    __nv_bfloat16 lo = __float2bfloat16(w - __bfloat162float(hi));
    int g = co >> 10;
    int within = co & 1023;
    int blk = within >> 3;
    int j = within & 7;
    size_t col = (size_t)blk * 32 + g * 8 + j;
    g_wsplit[(size_t)k * FH + col] = hi;
    g_wsplit[(size_t)(k + 1024) * FH + col] = lo;
}

// Wx split stacked: rows [0,1024): hi, [1024,2048): lo, [2048,3072): hi
__global__ void split_wx_kernel(const float* __restrict__ Wx) {
    int i = blockIdx.x * blockDim.x + threadIdx.x;
    if (i >= DD * FH) return;
    int k = i >> 12;
    int co = i & 4095;
    float w = Wx[i];
    __nv_bfloat16 hi = __float2bfloat16(w);
    __nv_bfloat16 lo = __float2bfloat16(w - __bfloat162float(hi));
    g_wxstack[(size_t)k * FH + co] = hi;
    g_wxstack[(size_t)(k + 1024) * FH + co] = lo;
    g_wxstack[(size_t)(k + 2048) * FH + co] = hi;
}

__global__ void split_x_kernel(const float* __restrict__ X) {
    size_t i = (size_t)blockIdx.x * blockDim.x + threadIdx.x;
    if (i >= (size_t)MM * DD) return;
    float v = X[i];
    __nv_bfloat16 hi = __float2bfloat16(v);
    g_xh[i] = hi;
    g_xl[i] = __float2bfloat16(v - __bfloat162float(hi));
}

// ---------------------------------------------------------------------------
// GEMM1 (split-bf16 MMA, unchanged from R7; ~1.3 ms, L2-bound)
// ---------------------------------------------------------------------------
#define G1_ASTR 40
#define G1_BSTR 136
#define G1_ABYTES (128 * G1_ASTR * 2)
#define G1_BBYTES (32 * G1_BSTR * 2)
#define G1_STAGE  (G1_ABYTES + G1_BBYTES)
#define G1_SMEM   (3 * G1_STAGE)
#define G1_NSLAB  96

__global__ __launch_bounds__(256) void gemm1_mma(const float* __restrict__ b) {
    extern __shared__ __align__(16) char sm1[];

    const int tid = threadIdx.x;
    const int lane = tid & 31;
    const int wid = tid >> 5;
    const int warp_m = wid >> 1;
    const int warp_n = wid & 1;
    const int m0 = blockIdx.y * 128;
    const int n0 = blockIdx.x * 128;

    const int lr = lane & 7;
    const int lg = lane >> 3;
    const int a_row_off = ((lg & 1) << 3) + lr;
    const int a_k_off = (lg >> 1) << 3;
    const int bt_row = lr + ((lg & 1) << 3);
    const int bt_c8 = (lane >> 4) << 3;

    float d[2][8][4];
#pragma unroll
    for (int mt = 0; mt < 2; mt++)
#pragma unroll
        for (int nt = 0; nt < 8; nt++)
#pragma unroll
            for (int r = 0; r < 4; r++) d[mt][nt][r] = 0.0f;

    auto prefetch = [&](int sp) {
        char* stg = sm1 + (sp % 3) * G1_STAGE;
        __nv_bfloat16* As = (__nv_bfloat16*)stg;
        __nv_bfloat16* Bs = (__nv_bfloat16*)(stg + G1_ABYTES);
        const __nv_bfloat16* asrc = (sp < 64) ? g_xh : g_xl;
        const int kin = (sp * 32) & 1023;
#pragma unroll
        for (int i = 0; i < 2; i++) {
            int idx = tid + i * 256;
            int row = idx >> 2, ch = idx & 3;
            cp16(&As[row * G1_ASTR + ch * 8],
                 &asrc[(size_t)(m0 + row) * DD + kin + ch * 8]);
        }
#pragma unroll
        for (int i = 0; i < 2; i++) {
            int idx = tid + i * 256;
            int row = idx >> 4, ch = idx & 15;
            cp16(&Bs[row * G1_BSTR + ch * 8],
                 &g_wxstack[(size_t)(sp * 32 + row) * FH + n0 + ch * 8]);
        }
        asm volatile("cp.async.commit_group;");
    };

    prefetch(0);
    prefetch(1);

    for (int s = 0; s < G1_NSLAB; s++) {
        asm volatile("cp.async.wait_group 1;");
        __syncthreads();
        if (s + 2 < G1_NSLAB) prefetch(s + 2);
        else asm volatile("cp.async.commit_group;");

        char* stg = sm1 + (s % 3) * G1_STAGE;
        const __nv_bfloat16* As = (const __nv_bfloat16*)stg;
        const __nv_bfloat16* Bs = (const __nv_bfloat16*)(stg + G1_ABYTES);

#pragma unroll
        for (int ks = 0; ks < 2; ks++) {
            const int kk0 = ks * 16;
            unsigned a[2][4];
#pragma unroll
            for (int mt = 0; mt < 2; mt++) {
                unsigned addr = s2u(&As[(warp_m * 32 + mt * 16 + a_row_off) * G1_ASTR
                                        + kk0 + a_k_off]);
                LDSM_X4(a[mt][0], a[mt][1], a[mt][2], a[mt][3], addr);
            }
            unsigned bf[4][4];
#pragma unroll
            for (int np = 0; np < 4; np++) {
                unsigned addr = s2u(&Bs[(kk0 + bt_row) * G1_BSTR
                                        + warp_n * 64 + np * 16 + bt_c8]);
                LDSM_X4T(bf[np][0], bf[np][1], bf[np][2], bf[np][3], addr);
            }
#pragma unroll
            for (int mt = 0; mt < 2; mt++)
#pragma unroll
                for (int nt = 0; nt < 8; nt++) {
                    unsigned b0 = bf[nt >> 1][(nt & 1) * 2 + 0];
                    unsigned b1 = bf[nt >> 1][(nt & 1) * 2 + 1];
                    MMA16816(d[mt][nt][0], d[mt][nt][1], d[mt][nt][2], d[mt][nt][3],
                             a[mt][0], a[mt][1], a[mt][2], a[mt][3], b0, b1);
                }
        }
    }

    const int r4 = lane >> 2;
    const int c2 = (lane & 3) * 2;
#pragma unroll
    for (int mt = 0; mt < 2; mt++) {
        int mbase = m0 + warp_m * 32 + mt * 16;
#pragma unroll
        for (int nt = 0; nt < 8; nt++) {
            int col = n0 + warp_n * 64 + nt * 8 + c2;
            float b0 = b[col], b1 = b[col + 1];
            int m = mbase + r4;
            int nb = m >> 9, tl = m & 511;
            float2 v0 = {d[mt][nt][0] + b0, d[mt][nt][1] + b1};
            *(float2*)&g_xz[(size_t)(tl * NB + nb) * FH + col] = v0;
            m += 8; nb = m >> 9; tl = m & 511;
            float2 v1 = {d[mt][nt][2] + b0, d[mt][nt][3] + b1};
            *(float2*)&g_xz[(size_t)(tl * NB + nb) * FH + col] = v1;
        }
    }
}

// ---------------------------------------------------------------------------
// Persistent recurrence kernel (R7 mainloop) with flag-based step sync:
//   - g_ready[t][g] gates each slab's h loads (group g = blocks g*32..g*32+31,
//     producing h cols [g*256,(g+1)*256))
//   - g_done[t] gates the h(t+1) write (WAR vs readers of h(t-1))
// No grid-wide barrier.
// ---------------------------------------------------------------------------
#define WS_STR 40    // bf16; 80 B rows
#define HS_STR 264   // bf16; 528 B rows (odd multiple of 16B)
#define KSLAB 256
#define HS_STAGE_B (64 * HS_STR * 2)                 // 33792
#define SMEM_WS_B (2048 * WS_STR * 2)                // 163840
#define P_SMEM (SMEM_WS_B + 2 * HS_STAGE_B)          // 231424

__global__ __launch_bounds__(512, 1) void lstm_persistent(float* __restrict__ out) {
    extern __shared__ __align__(16) char smp[];
    __nv_bfloat16* ws = (__nv_bfloat16*)smp;                  // [2048][WS_STR]
    __nv_bfloat16* hsm = (__nv_bfloat16*)(smp + SMEM_WS_B);   // 2 stages
    float* zbuf = (float*)(smp + SMEM_WS_B);                  // alias of stage 0

    const int tid = threadIdx.x;
    const int lane = tid & 31;
    const int wid = tid >> 5;
    const int warp_k = wid >> 3;        // 0..1
    const int warp_m = (wid >> 2) & 1;  // 0..1
    const int warp_c = wid & 3;         // 0..3
    const int blk = blockIdx.x;
    const int my_group = blk >> 5;      // which ready-group this block feeds

    // --- Load this block's W slice into SMEM (once) ---
    {
        const __nv_bfloat16* wsrc = g_wsplit + (size_t)blk * 32;
#pragma unroll
        for (int i = 0; i < 16; i++) {
            int c = tid + i * 512;
            int row = c >> 2, q = c & 3;
            *(uint4*)&ws[row * WS_STR + q * 8] =
                *(const uint4*)&wsrc[(size_t)row * FH + q * 8];
        }
    }
    __syncthreads();

    // ldmatrix lane addressing
    const int lr = lane & 7;
    const int lg = lane >> 3;
    const int a_row_off = ((lg & 1) << 3) + lr;
    const int a_k_off = (lg >> 1) << 3;
    const int b_krow = lane & 15;

    // epilogue mapping: 1 output per thread
    const int e_n = tid >> 3;
    const int e_j = tid & 7;
    const int J0 = blk * 8;
    float creg = 0.0f;

    for (int t = 0; t < TT; t++) {
        const int par = t & 1;
        const __nv_bfloat16* __restrict__ hh = g_hh[par];
        const __nv_bfloat16* __restrict__ hl = g_hl[par];

        // Early xz prefetch (DRAM latency hidden behind the slab loop)
        const float* xr = g_xz + (size_t)(t * NB + e_n) * FH + J0 + e_j;
        float x0 = __ldg(xr);
        float x1 = __ldg(xr + 1024);
        float x2 = __ldg(xr + 2048);
        float x3 = __ldg(xr + 3072);

        float d[2][4];
#pragma unroll
        for (int mt = 0; mt < 2; mt++)
#pragma unroll
            for (int r = 0; r < 4; r++) d[mt][r] = 0.0f;

        // Slabs: 0-3 h_hi (W_hi + W_lo), 4-7 h_lo (W_hi only).
        // Slab s needs h cols [(s&3)*256, +256) -> ready group (s&3).
        auto pf = [&](int s) {
            if (t > 0 && s < 4) spin_until(&g_ready[t][s], 32u);
            const __nv_bfloat16* src = (s < 4) ? hh : hl;
            const int hk = (s & 3) * KSLAB;
            __nv_bfloat16* dst = hsm + (s & 1) * 64 * HS_STR;
#pragma unroll
            for (int i = 0; i < 4; i++) {
                int idx = tid + i * 512;    // 2048 chunks of 16B
                int n = idx >> 5, ch = idx & 31;
                cp16(&dst[n * HS_STR + ch * 8], &src[n * HH + hk + ch * 8]);
            }
            asm volatile("cp.async.commit_group;");
        };

        pf(0);

        for (int s = 0; s < 8; s++) {
            asm volatile("cp.async.wait_group 0;");
            __syncthreads();
            if (s + 1 < 8) pf(s + 1);

            const __nv_bfloat16* hbuf = hsm + (s & 1) * 64 * HS_STR;
            const bool hiph = (s < 4);
            const int kw = (s & 3) * KSLAB;

#pragma unroll
            for (int ks = 0; ks < 8; ks++) {
                const int kk0 = warp_k * 128 + ks * 16;
                unsigned a[2][4];
#pragma unroll
                for (int mt = 0; mt < 2; mt++) {
                    unsigned addr = s2u(&hbuf[(warp_m * 32 + mt * 16 + a_row_off) * HS_STR
                                              + kk0 + a_k_off]);
                    LDSM_X4(a[mt][0], a[mt][1], a[mt][2], a[mt][3], addr);
                }
                {   // W_hi product
                    unsigned b0, b1;
                    unsigned addr = s2u(&ws[(kw + kk0 + b_krow) * WS_STR + warp_c * 8]);
                    LDSM_X2T(b0, b1, addr);
#pragma unroll
                    for (int mt = 0; mt < 2; mt++)
                        MMA16816(d[mt][0], d[mt][1], d[mt][2], d[mt][3],
                                 a[mt][0], a[mt][1], a[mt][2], a[mt][3], b0, b1);
                }
                if (hiph) {   // W_lo product
                    unsigned b0, b1;
                    unsigned addr = s2u(&ws[(1024 + kw + kk0 + b_krow) * WS_STR + warp_c * 8]);
                    LDSM_X2T(b0, b1, addr);
#pragma unroll
                    for (int mt = 0; mt < 2; mt++)
                        MMA16816(d[mt][0], d[mt][1], d[mt][2], d[mt][3],
                                 a[mt][0], a[mt][1], a[mt][2], a[mt][3], b0, b1);
                }
            }
        }
        __syncthreads();   // all compute done; zbuf (alias of stage 0) now safe

        // Signal: this block has finished READING h(t)
        if (tid == 0) red_release_add1(&g_done[t]);

        // Scatter partials: zbuf[warp_k][n][c]
        {
            const int r4 = lane >> 2;
            const int c2 = (lane & 3) * 2;
            const int c = warp_c * 8 + c2;
#pragma unroll
            for (int mt = 0; mt < 2; mt++) {
                int n = warp_m * 32 + mt * 16 + r4;
                zbuf[(warp_k * 64 + n) * 33 + c] = d[mt][0];
                zbuf[(warp_k * 64 + n) * 33 + c + 1] = d[mt][1];
                zbuf[(warp_k * 64 + n + 8) * 33 + c] = d[mt][2];
                zbuf[(warp_k * 64 + n + 8) * 33 + c + 1] = d[mt][3];
            }
        }
        __syncthreads();

        // Gate epilogue: 1 fixed (n, j) output per thread; c in register
        {
            const int n = e_n, col = J0 + e_j;
            float zi = zbuf[n * 33 + e_j +  0] + zbuf[(64 + n) * 33 + e_j +  0] + x0;
            float zf = zbuf[n * 33 + e_j +  8] + zbuf[(64 + n) * 33 + e_j +  8] + x1;
            float zo = zbuf[n * 33 + e_j + 16] + zbuf[(64 + n) * 33 + e_j + 16] + x2;
            float zg = zbuf[n * 33 + e_j + 24] + zbuf[(64 + n) * 33 + e_j + 24] + x3;

            float iv = 1.0f / (1.0f + expf(-zi));
            float fv = 1.0f / (1.0f + expf(-zf));
            float ov = 1.0f / (1.0f + expf(-zo));
            float gv = tanhf(zg);

            float cn = fv * creg + iv * gv;
            creg = cn;
            float hn = ov * tanhf(cn);

            // WAR gate: h(t+1) shares the buffer with h(t-1); wait until all
            // blocks have finished reading h(t-1).
            if (t > 0) spin_until(&g_done[t - 1], 128u);

            int hidx = n * HH + col;
            __nv_bfloat16 hi = __float2bfloat16(hn);
            g_hh[par ^ 1][hidx] = hi;
            g_hl[par ^ 1][hidx] = __float2bfloat16(hn - __bfloat162float(hi));
            out[((size_t)n * TT + t) * HH + col] = hn;
        }
        __syncthreads();   // all h writes done (and zbuf reads before next pf)

        // Publish h(t+1) for this block's column group
        if (tid == 0 && t + 1 < TT) red_release_add1(&g_ready[t + 1][my_group]);
    }
}

// ---------------------------------------------------------------------------
// Launcher (graph-capturable: kernel launches only)
// ---------------------------------------------------------------------------
extern "C" void kernel_launch(void* const* d_in, const int* in_sizes, int n_in,
                              void* d_out, int out_size) {
    const float* x  = (const float*)d_in[0];
    const float* h0 = (const float*)d_in[1];
    const float* Wx = (const float*)d_in[2];
    const float* Wh = (const float*)d_in[3];
    const float* b  = (const float*)d_in[4];
    float* out = (float*)d_out;

    static int attr_set = 0;
    if (!attr_set) {
        cudaFuncSetAttribute(lstm_persistent,
                             cudaFuncAttributeMaxDynamicSharedMemorySize, P_SMEM);
        cudaFuncSetAttribute(gemm1_mma,
                             cudaFuncAttributeMaxDynamicSharedMemorySize, G1_SMEM);
        attr_set = 1;
    }

    init_kernel<<<(NB * HH + 255) / 256, 256>>>(h0);
    split_wh_kernel<<<(DD * FH + 255) / 256, 256>>>(Wh);
    split_wx_kernel<<<(DD * FH + 255) / 256, 256>>>(Wx);
    split_x_kernel<<<((size_t)MM * DD + 511) / 512, 512>>>(x);

    dim3 g1(FH / 128, MM / 128);   // (32, 256)
    gemm1_mma<<<g1, 256, G1_SMEM>>>(b);

    lstm_persistent<<<128, 512, P_SMEM>>>(out);
}

// round 11
// speedup vs baseline: 1.1436x; 1.1436x over previous
#include <cuda_runtime.h>
#include <cuda_bf16.h>
#include <math.h>

#define NB 64
#define TT 512
#define DD 1024
#define HH 1024
#define FH 4096   // 4*H
#define MM 32768  // NB*TT

typedef unsigned long long ull;

// Scratch (device globals — no runtime allocation allowed)
__device__ float g_xz[(size_t)TT * NB * FH];              // (t, n, 4H) : 512 MB
__device__ __nv_bfloat16 g_wsplit[(size_t)2048 * FH];     // Wh hi|lo, cols permuted
__device__ __nv_bfloat16 g_wxstack[(size_t)3072 * FH];    // [Wx_hi; Wx_lo; Wx_hi]
__device__ __nv_bfloat16 g_xh[(size_t)MM * DD];           // x hi
__device__ __nv_bfloat16 g_xl[(size_t)MM * DD];           // x lo
__device__ __nv_bfloat16 g_hh[2][NB * HH];                // h hi, double-buffered
__device__ __nv_bfloat16 g_hl[2][NB * HH];                // h lo
__device__ unsigned g_bar_count;
__device__ unsigned g_bar_phase;

// ---- helpers ----------------------------------------------------------------
__device__ __forceinline__ unsigned s2u(const void* p) {
    return (unsigned)__cvta_generic_to_shared(p);
}
__device__ __forceinline__ void cp16(void* s, const void* g) {
    asm volatile("cp.async.cg.shared.global [%0], [%1], 16;" :: "r"(s2u(s)), "l"(g));
}
__device__ __forceinline__ unsigned ld_acquire(unsigned* p) {
    unsigned v;
    asm volatile("ld.acquire.gpu.u32 %0, [%1];" : "=r"(v) : "l"(p) : "memory");
    return v;
}
__device__ __forceinline__ void st_release(unsigned* p, unsigned v) {
    asm volatile("st.release.gpu.u32 [%0], %1;" :: "l"(p), "r"(v) : "memory");
}
#define LDSM_X4(r0, r1, r2, r3, addr) \
    asm volatile("ldmatrix.sync.aligned.m8n8.x4.shared.b16 {%0,%1,%2,%3}, [%4];" \
                 : "=r"(r0), "=r"(r1), "=r"(r2), "=r"(r3) : "r"(addr))
#define LDSM_X2T(r0, r1, addr) \
    asm volatile("ldmatrix.sync.aligned.m8n8.x2.trans.shared.b16 {%0,%1}, [%2];" \
                 : "=r"(r0), "=r"(r1) : "r"(addr))
#define LDSM_X4T(r0, r1, r2, r3, addr) \
    asm volatile("ldmatrix.sync.aligned.m8n8.x4.trans.shared.b16 {%0,%1,%2,%3}, [%4];" \
                 : "=r"(r0), "=r"(r1), "=r"(r2), "=r"(r3) : "r"(addr))
#define MMA16816(d0, d1, d2, d3, a0, a1, a2, a3, b0, b1) \
    asm volatile("mma.sync.aligned.m16n8k16.row.col.f32.bf16.bf16.f32 " \
                 "{%0,%1,%2,%3}, {%4,%5,%6,%7}, {%8,%9}, {%0,%1,%2,%3};" \
                 : "+f"(d0), "+f"(d1), "+f"(d2), "+f"(d3) \
                 : "r"(a0), "r"(a1), "r"(a2), "r"(a3), "r"(b0), "r"(b1))

// ---------------------------------------------------------------------------
// Init / precompute kernels
// ---------------------------------------------------------------------------
__global__ void init_kernel(const float* __restrict__ h0) {
    int i = blockIdx.x * blockDim.x + threadIdx.x;
    if (i == 0) { g_bar_count = 0; g_bar_phase = 0; }
    if (i < NB * HH) {
        float v = h0[i];
        __nv_bfloat16 hi = __float2bfloat16(v);
        g_hh[0][i] = hi;
        g_hl[0][i] = __float2bfloat16(v - __bfloat162float(hi));
    }
}

// Wh split + block-column permute: col_new = blk*32 + g*8 + j
__global__ void split_wh_kernel(const float* __restrict__ Wh) {
    int i = blockIdx.x * blockDim.x + threadIdx.x;
    if (i >= DD * FH) return;
    int k = i >> 12;
    int co = i & 4095;
    float w = Wh[i];
    __nv_bfloat16 hi = __float2bfloat16(w);
    __nv_bfloat16 lo = __float2bfloat16(w - __bfloat162float(hi));
    int g = co >> 10;
    int within = co & 1023;
    int blk = within >> 3;
    int j = within & 7;
    size_t col = (size_t)blk * 32 + g * 8 + j;
    g_wsplit[(size_t)k * FH + col] = hi;
    g_wsplit[(size_t)(k + 1024) * FH + col] = lo;
}

// Wx split stacked: rows [0,1024): hi, [1024,2048): lo, [2048,3072): hi
__global__ void split_wx_kernel(const float* __restrict__ Wx) {
    int i = blockIdx.x * blockDim.x + threadIdx.x;
    if (i >= DD * FH) return;
    int k = i >> 12;
    int co = i & 4095;
    float w = Wx[i];
    __nv_bfloat16 hi = __float2bfloat16(w);
    __nv_bfloat16 lo = __float2bfloat16(w - __bfloat162float(hi));
    g_wxstack[(size_t)k * FH + co] = hi;
    g_wxstack[(size_t)(k + 1024) * FH + co] = lo;
    g_wxstack[(size_t)(k + 2048) * FH + co] = hi;
}

__global__ void split_x_kernel(const float* __restrict__ X) {
    size_t i = (size_t)blockIdx.x * blockDim.x + threadIdx.x;
    if (i >= (size_t)MM * DD) return;
    float v = X[i];
    __nv_bfloat16 hi = __float2bfloat16(v);
    g_xh[i] = hi;
    g_xl[i] = __float2bfloat16(v - __bfloat162float(hi));
}

// ---------------------------------------------------------------------------
// GEMM1 (split-bf16 MMA, unchanged from R7; L2-bound ~1.3 ms)
// ---------------------------------------------------------------------------
#define G1_ASTR 40
#define G1_BSTR 136
#define G1_ABYTES (128 * G1_ASTR * 2)
#define G1_BBYTES (32 * G1_BSTR * 2)
#define G1_STAGE  (G1_ABYTES + G1_BBYTES)
#define G1_SMEM   (3 * G1_STAGE)
#define G1_NSLAB  96

__global__ __launch_bounds__(256) void gemm1_mma(const float* __restrict__ b) {
    extern __shared__ __align__(16) char sm1[];

    const int tid = threadIdx.x;
    const int lane = tid & 31;
    const int wid = tid >> 5;
    const int warp_m = wid >> 1;
    const int warp_n = wid & 1;
    const int m0 = blockIdx.y * 128;
    const int n0 = blockIdx.x * 128;

    const int lr = lane & 7;
    const int lg = lane >> 3;
    const int a_row_off = ((lg & 1) << 3) + lr;
    const int a_k_off = (lg >> 1) << 3;
    const int bt_row = lr + ((lg & 1) << 3);
    const int bt_c8 = (lane >> 4) << 3;

    float d[2][8][4];
#pragma unroll
    for (int mt = 0; mt < 2; mt++)
#pragma unroll
        for (int nt = 0; nt < 8; nt++)
#pragma unroll
            for (int r = 0; r < 4; r++) d[mt][nt][r] = 0.0f;

    auto prefetch = [&](int sp) {
        char* stg = sm1 + (sp % 3) * G1_STAGE;
        __nv_bfloat16* As = (__nv_bfloat16*)stg;
        __nv_bfloat16* Bs = (__nv_bfloat16*)(stg + G1_ABYTES);
        const __nv_bfloat16* asrc = (sp < 64) ? g_xh : g_xl;
        const int kin = (sp * 32) & 1023;
#pragma unroll
        for (int i = 0; i < 2; i++) {
            int idx = tid + i * 256;
            int row = idx >> 2, ch = idx & 3;
            cp16(&As[row * G1_ASTR + ch * 8],
                 &asrc[(size_t)(m0 + row) * DD + kin + ch * 8]);
        }
#pragma unroll
        for (int i = 0; i < 2; i++) {
            int idx = tid + i * 256;
            int row = idx >> 4, ch = idx & 15;
            cp16(&Bs[row * G1_BSTR + ch * 8],
                 &g_wxstack[(size_t)(sp * 32 + row) * FH + n0 + ch * 8]);
        }
        asm volatile("cp.async.commit_group;");
    };

    prefetch(0);
    prefetch(1);

    for (int s = 0; s < G1_NSLAB; s++) {
        asm volatile("cp.async.wait_group 1;");
        __syncthreads();
        if (s + 2 < G1_NSLAB) prefetch(s + 2);
        else asm volatile("cp.async.commit_group;");

        char* stg = sm1 + (s % 3) * G1_STAGE;
        const __nv_bfloat16* As = (const __nv_bfloat16*)stg;
        const __nv_bfloat16* Bs = (const __nv_bfloat16*)(stg + G1_ABYTES);

#pragma unroll
        for (int ks = 0; ks < 2; ks++) {
            const int kk0 = ks * 16;
            unsigned a[2][4];
#pragma unroll
            for (int mt = 0; mt < 2; mt++) {
                unsigned addr = s2u(&As[(warp_m * 32 + mt * 16 + a_row_off) * G1_ASTR
                                        + kk0 + a_k_off]);
                LDSM_X4(a[mt][0], a[mt][1], a[mt][2], a[mt][3], addr);
            }
            unsigned bf[4][4];
#pragma unroll
            for (int np = 0; np < 4; np++) {
                unsigned addr = s2u(&Bs[(kk0 + bt_row) * G1_BSTR
                                        + warp_n * 64 + np * 16 + bt_c8]);
                LDSM_X4T(bf[np][0], bf[np][1], bf[np][2], bf[np][3], addr);
            }
#pragma unroll
            for (int mt = 0; mt < 2; mt++)
#pragma unroll
                for (int nt = 0; nt < 8; nt++) {
                    unsigned b0 = bf[nt >> 1][(nt & 1) * 2 + 0];
                    unsigned b1 = bf[nt >> 1][(nt & 1) * 2 + 1];
                    MMA16816(d[mt][nt][0], d[mt][nt][1], d[mt][nt][2], d[mt][nt][3],
                             a[mt][0], a[mt][1], a[mt][2], a[mt][3], b0, b1);
                }
        }
    }

    const int r4 = lane >> 2;
    const int c2 = (lane & 3) * 2;
#pragma unroll
    for (int mt = 0; mt < 2; mt++) {
        int mbase = m0 + warp_m * 32 + mt * 16;
#pragma unroll
        for (int nt = 0; nt < 8; nt++) {
            int col = n0 + warp_n * 64 + nt * 8 + c2;
            float b0 = b[col], b1 = b[col + 1];
            int m = mbase + r4;
            int nb = m >> 9, tl = m & 511;
            float2 v0 = {d[mt][nt][0] + b0, d[mt][nt][1] + b1};
            *(float2*)&g_xz[(size_t)(tl * NB + nb) * FH + col] = v0;
            m += 8; nb = m >> 9; tl = m & 511;
            float2 v1 = {d[mt][nt][2] + b0, d[mt][nt][3] + b1};
            *(float2*)&g_xz[(size_t)(tl * NB + nb) * FH + col] = v1;
        }
    }
}

// ---------------------------------------------------------------------------
// Persistent recurrence kernel. 128 blocks x 1024 threads (32 warps:
// 4(k-split) x 2(m) x 4(c)). W resident in SMEM; h in 256-wide slabs,
// 2-stage double-buffered cp.async, one syncthreads per slab.
// Split-bf16: z = h_hi*W_hi + h_hi*W_lo + h_lo*W_hi.
// ---------------------------------------------------------------------------
#define WS_STR 40    // bf16; 80 B rows
#define HS_STR 264   // bf16; 528 B rows (odd multiple of 16B)
#define KSLAB 256
#define HS_STAGE_B (64 * HS_STR * 2)                 // 33792
#define SMEM_WS_B (2048 * WS_STR * 2)                // 163840
#define P_SMEM (SMEM_WS_B + 2 * HS_STAGE_B)          // 231424

__global__ __launch_bounds__(1024, 1) void lstm_persistent(float* __restrict__ out) {
    extern __shared__ __align__(16) char smp[];
    __nv_bfloat16* ws = (__nv_bfloat16*)smp;                  // [2048][WS_STR]
    __nv_bfloat16* hsm = (__nv_bfloat16*)(smp + SMEM_WS_B);   // 2 stages
    float* zbuf = (float*)(smp + SMEM_WS_B);                  // alias of stage 0: [4][64][33]

    const int tid = threadIdx.x;
    const int lane = tid & 31;
    const int wid = tid >> 5;
    const int warp_k = wid >> 3;        // 0..3
    const int warp_m = (wid >> 2) & 1;  // 0..1
    const int warp_c = wid & 3;         // 0..3
    const int blk = blockIdx.x;

    // --- Load this block's W slice into SMEM (once) ---
    {
        const __nv_bfloat16* wsrc = g_wsplit + (size_t)blk * 32;
#pragma unroll
        for (int i = 0; i < 8; i++) {
            int c = tid + i * 1024;
            int row = c >> 2, q = c & 3;
            *(uint4*)&ws[row * WS_STR + q * 8] =
                *(const uint4*)&wsrc[(size_t)row * FH + q * 8];
        }
    }
    __syncthreads();

    // ldmatrix lane addressing
    const int lr = lane & 7;
    const int lg = lane >> 3;
    const int a_row_off = ((lg & 1) << 3) + lr;
    const int a_k_off = (lg >> 1) << 3;
    const int b_krow = lane & 15;

    // epilogue mapping: threads 0..511 handle one (n, j) output each
    const bool epi = (tid < 512);
    const int e_n = tid >> 3;
    const int e_j = tid & 7;
    const int J0 = blk * 8;
    float creg = 0.0f;

    for (int t = 0; t < TT; t++) {
        const int par = t & 1;
        const __nv_bfloat16* __restrict__ hh = g_hh[par];
        const __nv_bfloat16* __restrict__ hl = g_hl[par];

        // Early xz prefetch (DRAM latency hidden behind the slab loop)
        float x0 = 0.f, x1 = 0.f, x2 = 0.f, x3 = 0.f;
        if (epi) {
            const float* xr = g_xz + (size_t)(t * NB + e_n) * FH + J0 + e_j;
            x0 = __ldg(xr);
            x1 = __ldg(xr + 1024);
            x2 = __ldg(xr + 2048);
            x3 = __ldg(xr + 3072);
        }

        float d[2][4];
#pragma unroll
        for (int mt = 0; mt < 2; mt++)
#pragma unroll
            for (int r = 0; r < 4; r++) d[mt][r] = 0.0f;

        // Slabs: 0-3 h_hi (W_hi + W_lo), 4-7 h_lo (W_hi only)
        auto pf = [&](int s) {
            const __nv_bfloat16* src = (s < 4) ? hh : hl;
            const int hk = (s & 3) * KSLAB;
            __nv_bfloat16* dst = hsm + (s & 1) * 64 * HS_STR;
#pragma unroll
            for (int i = 0; i < 2; i++) {
                int idx = tid + i * 1024;   // 2048 chunks of 16B
                int n = idx >> 5, ch = idx & 31;
                cp16(&dst[n * HS_STR + ch * 8], &src[n * HH + hk + ch * 8]);
            }
            asm volatile("cp.async.commit_group;");
        };

        pf(0);

        for (int s = 0; s < 8; s++) {
            asm volatile("cp.async.wait_group 0;");
            __syncthreads();
            if (s + 1 < 8) pf(s + 1);

            const __nv_bfloat16* hbuf = hsm + (s & 1) * 64 * HS_STR;
            const bool hiph = (s < 4);
            const int kw = (s & 3) * KSLAB;

#pragma unroll
            for (int ks = 0; ks < 4; ks++) {
                const int kk0 = warp_k * 64 + ks * 16;
                unsigned a[2][4];
#pragma unroll
                for (int mt = 0; mt < 2; mt++) {
                    unsigned addr = s2u(&hbuf[(warp_m * 32 + mt * 16 + a_row_off) * HS_STR
                                              + kk0 + a_k_off]);
                    LDSM_X4(a[mt][0], a[mt][1], a[mt][2], a[mt][3], addr);
                }
                {   // W_hi product
                    unsigned b0, b1;
                    unsigned addr = s2u(&ws[(kw + kk0 + b_krow) * WS_STR + warp_c * 8]);
                    LDSM_X2T(b0, b1, addr);
#pragma unroll
                    for (int mt = 0; mt < 2; mt++)
                        MMA16816(d[mt][0], d[mt][1], d[mt][2], d[mt][3],
                                 a[mt][0], a[mt][1], a[mt][2], a[mt][3], b0, b1);
                }
                if (hiph) {   // W_lo product
                    unsigned b0, b1;
                    unsigned addr = s2u(&ws[(1024 + kw + kk0 + b_krow) * WS_STR + warp_c * 8]);
                    LDSM_X2T(b0, b1, addr);
#pragma unroll
                    for (int mt = 0; mt < 2; mt++)
                        MMA16816(d[mt][0], d[mt][1], d[mt][2], d[mt][3],
                                 a[mt][0], a[mt][1], a[mt][2], a[mt][3], b0, b1);
                }
            }
        }
        __syncthreads();   // all compute done; zbuf (alias of stage 0) now safe

        // Scatter partials: zbuf[warp_k][n][c]
        {
            const int r4 = lane >> 2;
            const int c2 = (lane & 3) * 2;
            const int c = warp_c * 8 + c2;
            float* zb = zbuf + warp_k * (64 * 33);
#pragma unroll
            for (int mt = 0; mt < 2; mt++) {
                int n = warp_m * 32 + mt * 16 + r4;
                zb[n * 33 + c] = d[mt][0];
                zb[n * 33 + c + 1] = d[mt][1];
                zb[(n + 8) * 33 + c] = d[mt][2];
                zb[(n + 8) * 33 + c + 1] = d[mt][3];
            }
        }
        __syncthreads();

        // Gate epilogue: threads 0..511, one (n, j) each; c in register
        if (epi) {
            const int n = e_n, col = J0 + e_j;
            float zi = x0, zf = x1, zo = x2, zg = x3;
#pragma unroll
            for (int g = 0; g < 4; g++) {
                const float* zb = zbuf + g * (64 * 33) + n * 33 + e_j;
                zi += zb[0];
                zf += zb[8];
                zo += zb[16];
                zg += zb[24];
            }

            float iv = 1.0f / (1.0f + expf(-zi));
            float fv = 1.0f / (1.0f + expf(-zf));
            float ov = 1.0f / (1.0f + expf(-zo));
            float gv = tanhf(zg);

            float cn = fv * creg + iv * gv;
            creg = cn;
            float hn = ov * tanhf(cn);

            int hidx = n * HH + col;
            __nv_bfloat16 hi = __float2bfloat16(hn);
            g_hh[par ^ 1][hidx] = hi;
            g_hl[par ^ 1][hidx] = __float2bfloat16(hn - __bfloat162float(hi));
            out[((size_t)n * TT + t) * HH + col] = hn;
        }

        // Grid-wide barrier
        if (t + 1 < TT) {
            __syncthreads();
            if (tid == 0) {
                const unsigned target = (unsigned)(t + 1);
                __threadfence();
                unsigned old = atomicAdd(&g_bar_count, 1);
                if (old == gridDim.x - 1) {
                    g_bar_count = 0;
                    st_release(&g_bar_phase, target);
                } else {
                    while (ld_acquire(&g_bar_phase) < target) {}
                }
            }
            __syncthreads();
        }
    }
}

// ---------------------------------------------------------------------------
// Launcher (graph-capturable: kernel launches only)
// ---------------------------------------------------------------------------
extern "C" void kernel_launch(void* const* d_in, const int* in_sizes, int n_in,
                              void* d_out, int out_size) {
    const float* x  = (const float*)d_in[0];
    const float* h0 = (const float*)d_in[1];
    const float* Wx = (const float*)d_in[2];
    const float* Wh = (const float*)d_in[3];
    const float* b  = (const float*)d_in[4];
    float* out = (float*)d_out;

    static int attr_set = 0;
    if (!attr_set) {
        cudaFuncSetAttribute(lstm_persistent,
                             cudaFuncAttributeMaxDynamicSharedMemorySize, P_SMEM);
        cudaFuncSetAttribute(gemm1_mma,
                             cudaFuncAttributeMaxDynamicSharedMemorySize, G1_SMEM);
        attr_set = 1;
    }

    init_kernel<<<(NB * HH + 255) / 256, 256>>>(h0);
    split_wh_kernel<<<(DD * FH + 255) / 256, 256>>>(Wh);
    split_wx_kernel<<<(DD * FH + 255) / 256, 256>>>(Wx);
    split_x_kernel<<<((size_t)MM * DD + 511) / 512, 512>>>(x);

    dim3 g1(FH / 128, MM / 128);   // (32, 256)
    gemm1_mma<<<g1, 256, G1_SMEM>>>(b);

    lstm_persistent<<<128, 1024, P_SMEM>>>(out);
}

// round 12
// speedup vs baseline: 1.1775x; 1.0297x over previous
#include <cuda_runtime.h>
#include <cuda_bf16.h>
#include <math.h>

#define NB 64
#define TT 512
#define DD 1024
#define HH 1024
#define FH 4096   // 4*H
#define MM 32768  // NB*TT

typedef unsigned long long ull;

// Scratch (device globals — no runtime allocation allowed)
__device__ float g_xz[(size_t)TT * NB * FH];              // (t, n, 4H) : 512 MB
__device__ __nv_bfloat16 g_wsplit[(size_t)2048 * FH];     // Wh hi|lo, cols permuted
__device__ __nv_bfloat16 g_wxstack[(size_t)3072 * FH];    // [Wx_hi; Wx_lo; Wx_hi]
__device__ __nv_bfloat16 g_xh[(size_t)MM * DD];           // x hi
__device__ __nv_bfloat16 g_xl[(size_t)MM * DD];           // x lo
__device__ __nv_bfloat16 g_hh[2][NB * HH];                // h hi, double-buffered
__device__ __nv_bfloat16 g_hl[2][NB * HH];                // h lo
// Barrier v2: per-block arrival slots + broadcast phase (monotonic counters)
__device__ unsigned g_arrive[128];
__device__ unsigned g_phase;

// ---- helpers ----------------------------------------------------------------
__device__ __forceinline__ unsigned s2u(const void* p) {
    return (unsigned)__cvta_generic_to_shared(p);
}
__device__ __forceinline__ void cp16(void* s, const void* g) {
    asm volatile("cp.async.cg.shared.global [%0], [%1], 16;" :: "r"(s2u(s)), "l"(g));
}
__device__ __forceinline__ unsigned ld_acquire(const unsigned* p) {
    unsigned v;
    asm volatile("ld.acquire.gpu.u32 %0, [%1];" : "=r"(v) : "l"(p) : "memory");
    return v;
}
__device__ __forceinline__ void st_release(unsigned* p, unsigned v) {
    asm volatile("st.release.gpu.u32 [%0], %1;" :: "l"(p), "r"(v) : "memory");
}
__device__ __forceinline__ void spin_until(const unsigned* p, unsigned target) {
    while (ld_acquire(p) < target) {}
}
// Fast, accurate gates: MUFU.EX2 + MUFU.RCP paths, flag-independent
__device__ __forceinline__ float fsig(float x) {
    return __fdividef(1.0f, 1.0f + __expf(-x));
}
__device__ __forceinline__ float ftanh(float x) {
    return __fmaf_rn(2.0f, __fdividef(1.0f, 1.0f + __expf(-2.0f * x)), -1.0f);
}
#define LDSM_X4(r0, r1, r2, r3, addr) \
    asm volatile("ldmatrix.sync.aligned.m8n8.x4.shared.b16 {%0,%1,%2,%3}, [%4];" \
                 : "=r"(r0), "=r"(r1), "=r"(r2), "=r"(r3) : "r"(addr))
#define LDSM_X2T(r0, r1, addr) \
    asm volatile("ldmatrix.sync.aligned.m8n8.x2.trans.shared.b16 {%0,%1}, [%2];" \
                 : "=r"(r0), "=r"(r1) : "r"(addr))
#define LDSM_X4T(r0, r1, r2, r3, addr) \
    asm volatile("ldmatrix.sync.aligned.m8n8.x4.trans.shared.b16 {%0,%1,%2,%3}, [%4];" \
                 : "=r"(r0), "=r"(r1), "=r"(r2), "=r"(r3) : "r"(addr))
#define MMA16816(d0, d1, d2, d3, a0, a1, a2, a3, b0, b1) \
    asm volatile("mma.sync.aligned.m16n8k16.row.col.f32.bf16.bf16.f32 " \
                 "{%0,%1,%2,%3}, {%4,%5,%6,%7}, {%8,%9}, {%0,%1,%2,%3};" \
                 : "+f"(d0), "+f"(d1), "+f"(d2), "+f"(d3) \
                 : "r"(a0), "r"(a1), "r"(a2), "r"(a3), "r"(b0), "r"(b1))

// ---------------------------------------------------------------------------
// Init / precompute kernels
// ---------------------------------------------------------------------------
__global__ void init_kernel(const float* __restrict__ h0) {
    int i = blockIdx.x * blockDim.x + threadIdx.x;
    if (i < 128) g_arrive[i] = 0;
    if (i == 128) g_phase = 0;
    if (i < NB * HH) {
        float v = h0[i];
        __nv_bfloat16 hi = __float2bfloat16(v);
        g_hh[0][i] = hi;
        g_hl[0][i] = __float2bfloat16(v - __bfloat162float(hi));
    }
}

// Wh split + block-column permute: col_new = blk*32 + g*8 + j
__global__ void split_wh_kernel(const float* __restrict__ Wh) {
    int i = blockIdx.x * blockDim.x + threadIdx.x;
    if (i >= DD * FH) return;
    int k = i >> 12;
    int co = i & 4095;
    float w = Wh[i];
    __nv_bfloat16 hi = __float2bfloat16(w);
    __nv_bfloat16 lo = __float2bfloat16(w - __bfloat162float(hi));
    int g = co >> 10;
    int within = co & 1023;
    int blk = within >> 3;
    int j = within & 7;
    size_t col = (size_t)blk * 32 + g * 8 + j;
    g_wsplit[(size_t)k * FH + col] = hi;
    g_wsplit[(size_t)(k + 1024) * FH + col] = lo;
}

// Wx split stacked: rows [0,1024): hi, [1024,2048): lo, [2048,3072): hi
__global__ void split_wx_kernel(const float* __restrict__ Wx) {
    int i = blockIdx.x * blockDim.x + threadIdx.x;
    if (i >= DD * FH) return;
    int k = i >> 12;
    int co = i & 4095;
    float w = Wx[i];
    __nv_bfloat16 hi = __float2bfloat16(w);
    __nv_bfloat16 lo = __float2bfloat16(w - __bfloat162float(hi));
    g_wxstack[(size_t)k * FH + co] = hi;
    g_wxstack[(size_t)(k + 1024) * FH + co] = lo;
    g_wxstack[(size_t)(k + 2048) * FH + co] = hi;
}

__global__ void split_x_kernel(const float* __restrict__ X) {
    size_t i = (size_t)blockIdx.x * blockDim.x + threadIdx.x;
    if (i >= (size_t)MM * DD) return;
    float v = X[i];
    __nv_bfloat16 hi = __float2bfloat16(v);
    g_xh[i] = hi;
    g_xl[i] = __float2bfloat16(v - __bfloat162float(hi));
}

// ---------------------------------------------------------------------------
// GEMM1 (split-bf16 MMA, unchanged; L2-bound ~1.3 ms)
// ---------------------------------------------------------------------------
#define G1_ASTR 40
#define G1_BSTR 136
#define G1_ABYTES (128 * G1_ASTR * 2)
#define G1_BBYTES (32 * G1_BSTR * 2)
#define G1_STAGE  (G1_ABYTES + G1_BBYTES)
#define G1_SMEM   (3 * G1_STAGE)
#define G1_NSLAB  96

__global__ __launch_bounds__(256) void gemm1_mma(const float* __restrict__ b) {
    extern __shared__ __align__(16) char sm1[];

    const int tid = threadIdx.x;
    const int lane = tid & 31;
    const int wid = tid >> 5;
    const int warp_m = wid >> 1;
    const int warp_n = wid & 1;
    const int m0 = blockIdx.y * 128;
    const int n0 = blockIdx.x * 128;

    const int lr = lane & 7;
    const int lg = lane >> 3;
    const int a_row_off = ((lg & 1) << 3) + lr;
    const int a_k_off = (lg >> 1) << 3;
    const int bt_row = lr + ((lg & 1) << 3);
    const int bt_c8 = (lane >> 4) << 3;

    float d[2][8][4];
#pragma unroll
    for (int mt = 0; mt < 2; mt++)
#pragma unroll
        for (int nt = 0; nt < 8; nt++)
#pragma unroll
            for (int r = 0; r < 4; r++) d[mt][nt][r] = 0.0f;

    auto prefetch = [&](int sp) {
        char* stg = sm1 + (sp % 3) * G1_STAGE;
        __nv_bfloat16* As = (__nv_bfloat16*)stg;
        __nv_bfloat16* Bs = (__nv_bfloat16*)(stg + G1_ABYTES);
        const __nv_bfloat16* asrc = (sp < 64) ? g_xh : g_xl;
        const int kin = (sp * 32) & 1023;
#pragma unroll
        for (int i = 0; i < 2; i++) {
            int idx = tid + i * 256;
            int row = idx >> 2, ch = idx & 3;
            cp16(&As[row * G1_ASTR + ch * 8],
                 &asrc[(size_t)(m0 + row) * DD + kin + ch * 8]);
        }
#pragma unroll
        for (int i = 0; i < 2; i++) {
            int idx = tid + i * 256;
            int row = idx >> 4, ch = idx & 15;
            cp16(&Bs[row * G1_BSTR + ch * 8],
                 &g_wxstack[(size_t)(sp * 32 + row) * FH + n0 + ch * 8]);
        }
        asm volatile("cp.async.commit_group;");
    };

    prefetch(0);
    prefetch(1);

    for (int s = 0; s < G1_NSLAB; s++) {
        asm volatile("cp.async.wait_group 1;");
        __syncthreads();
        if (s + 2 < G1_NSLAB) prefetch(s + 2);
        else asm volatile("cp.async.commit_group;");

        char* stg = sm1 + (s % 3) * G1_STAGE;
        const __nv_bfloat16* As = (const __nv_bfloat16*)stg;
        const __nv_bfloat16* Bs = (const __nv_bfloat16*)(stg + G1_ABYTES);

#pragma unroll
        for (int ks = 0; ks < 2; ks++) {
            const int kk0 = ks * 16;
            unsigned a[2][4];
#pragma unroll
            for (int mt = 0; mt < 2; mt++) {
                unsigned addr = s2u(&As[(warp_m * 32 + mt * 16 + a_row_off) * G1_ASTR
                                        + kk0 + a_k_off]);
                LDSM_X4(a[mt][0], a[mt][1], a[mt][2], a[mt][3], addr);
            }
            unsigned bf[4][4];
#pragma unroll
            for (int np = 0; np < 4; np++) {
                unsigned addr = s2u(&Bs[(kk0 + bt_row) * G1_BSTR
                                        + warp_n * 64 + np * 16 + bt_c8]);
                LDSM_X4T(bf[np][0], bf[np][1], bf[np][2], bf[np][3], addr);
            }
#pragma unroll
            for (int mt = 0; mt < 2; mt++)
#pragma unroll
                for (int nt = 0; nt < 8; nt++) {
                    unsigned b0 = bf[nt >> 1][(nt & 1) * 2 + 0];
                    unsigned b1 = bf[nt >> 1][(nt & 1) * 2 + 1];
                    MMA16816(d[mt][nt][0], d[mt][nt][1], d[mt][nt][2], d[mt][nt][3],
                             a[mt][0], a[mt][1], a[mt][2], a[mt][3], b0, b1);
                }
        }
    }

    const int r4 = lane >> 2;
    const int c2 = (lane & 3) * 2;
#pragma unroll
    for (int mt = 0; mt < 2; mt++) {
        int mbase = m0 + warp_m * 32 + mt * 16;
#pragma unroll
        for (int nt = 0; nt < 8; nt++) {
            int col = n0 + warp_n * 64 + nt * 8 + c2;
            float b0 = b[col], b1 = b[col + 1];
            int m = mbase + r4;
            int nb = m >> 9, tl = m & 511;
            float2 v0 = {d[mt][nt][0] + b0, d[mt][nt][1] + b1};
            *(float2*)&g_xz[(size_t)(tl * NB + nb) * FH + col] = v0;
            m += 8; nb = m >> 9; tl = m & 511;
            float2 v1 = {d[mt][nt][2] + b0, d[mt][nt][3] + b1};
            *(float2*)&g_xz[(size_t)(tl * NB + nb) * FH + col] = v1;
        }
    }
}

// ---------------------------------------------------------------------------
// Persistent recurrence kernel (R7 mainloop, 512 threads) with:
//   - barrier v2 (per-block arrival slots, block-0 aggregator, phase bcast)
//   - fast gate math (fsig/ftanh)
// ---------------------------------------------------------------------------
#define WS_STR 40    // bf16; 80 B rows
#define HS_STR 264   // bf16; 528 B rows (odd multiple of 16B)
#define KSLAB 256
#define HS_STAGE_B (64 * HS_STR * 2)                 // 33792
#define SMEM_WS_B (2048 * WS_STR * 2)                // 163840
#define P_SMEM (SMEM_WS_B + 2 * HS_STAGE_B)          // 231424

__global__ __launch_bounds__(512, 1) void lstm_persistent(float* __restrict__ out) {
    extern __shared__ __align__(16) char smp[];
    __nv_bfloat16* ws = (__nv_bfloat16*)smp;                  // [2048][WS_STR]
    __nv_bfloat16* hsm = (__nv_bfloat16*)(smp + SMEM_WS_B);   // 2 stages
    float* zbuf = (float*)(smp + SMEM_WS_B);                  // alias of stage 0

    const int tid = threadIdx.x;
    const int lane = tid & 31;
    const int wid = tid >> 5;
    const int warp_k = wid >> 3;        // 0..1
    const int warp_m = (wid >> 2) & 1;  // 0..1
    const int warp_c = wid & 3;         // 0..3
    const int blk = blockIdx.x;

    // --- Load this block's W slice into SMEM (once) ---
    {
        const __nv_bfloat16* wsrc = g_wsplit + (size_t)blk * 32;
#pragma unroll
        for (int i = 0; i < 16; i++) {
            int c = tid + i * 512;
            int row = c >> 2, q = c & 3;
            *(uint4*)&ws[row * WS_STR + q * 8] =
                *(const uint4*)&wsrc[(size_t)row * FH + q * 8];
        }
    }
    __syncthreads();

    // ldmatrix lane addressing
    const int lr = lane & 7;
    const int lg = lane >> 3;
    const int a_row_off = ((lg & 1) << 3) + lr;
    const int a_k_off = (lg >> 1) << 3;
    const int b_krow = lane & 15;

    // epilogue mapping: 1 output per thread
    const int e_n = tid >> 3;
    const int e_j = tid & 7;
    const int J0 = blk * 8;
    float creg = 0.0f;

    for (int t = 0; t < TT; t++) {
        const int par = t & 1;
        const __nv_bfloat16* __restrict__ hh = g_hh[par];
        const __nv_bfloat16* __restrict__ hl = g_hl[par];

        // Early xz prefetch (DRAM latency hidden behind the slab loop)
        const float* xr = g_xz + (size_t)(t * NB + e_n) * FH + J0 + e_j;
        float x0 = __ldg(xr);
        float x1 = __ldg(xr + 1024);
        float x2 = __ldg(xr + 2048);
        float x3 = __ldg(xr + 3072);

        float d[2][4];
#pragma unroll
        for (int mt = 0; mt < 2; mt++)
#pragma unroll
            for (int r = 0; r < 4; r++) d[mt][r] = 0.0f;

        // Slabs: 0-3 h_hi (W_hi + W_lo), 4-7 h_lo (W_hi only)
        auto pf = [&](int s) {
            const __nv_bfloat16* src = (s < 4) ? hh : hl;
            const int hk = (s & 3) * KSLAB;
            __nv_bfloat16* dst = hsm + (s & 1) * 64 * HS_STR;
#pragma unroll
            for (int i = 0; i < 4; i++) {
                int idx = tid + i * 512;    // 2048 chunks of 16B
                int n = idx >> 5, ch = idx & 31;
                cp16(&dst[n * HS_STR + ch * 8], &src[n * HH + hk + ch * 8]);
            }
            asm volatile("cp.async.commit_group;");
        };

        pf(0);

        for (int s = 0; s < 8; s++) {
            asm volatile("cp.async.wait_group 0;");
            __syncthreads();
            if (s + 1 < 8) pf(s + 1);

            const __nv_bfloat16* hbuf = hsm + (s & 1) * 64 * HS_STR;
            const bool hiph = (s < 4);
            const int kw = (s & 3) * KSLAB;

#pragma unroll
            for (int ks = 0; ks < 8; ks++) {
                const int kk0 = warp_k * 128 + ks * 16;
                unsigned a[2][4];
#pragma unroll
                for (int mt = 0; mt < 2; mt++) {
                    unsigned addr = s2u(&hbuf[(warp_m * 32 + mt * 16 + a_row_off) * HS_STR
                                              + kk0 + a_k_off]);
                    LDSM_X4(a[mt][0], a[mt][1], a[mt][2], a[mt][3], addr);
                }
                {   // W_hi product
                    unsigned b0, b1;
                    unsigned addr = s2u(&ws[(kw + kk0 + b_krow) * WS_STR + warp_c * 8]);
                    LDSM_X2T(b0, b1, addr);
#pragma unroll
                    for (int mt = 0; mt < 2; mt++)
                        MMA16816(d[mt][0], d[mt][1], d[mt][2], d[mt][3],
                                 a[mt][0], a[mt][1], a[mt][2], a[mt][3], b0, b1);
                }
                if (hiph) {   // W_lo product
                    unsigned b0, b1;
                    unsigned addr = s2u(&ws[(1024 + kw + kk0 + b_krow) * WS_STR + warp_c * 8]);
                    LDSM_X2T(b0, b1, addr);
#pragma unroll
                    for (int mt = 0; mt < 2; mt++)
                        MMA16816(d[mt][0], d[mt][1], d[mt][2], d[mt][3],
                                 a[mt][0], a[mt][1], a[mt][2], a[mt][3], b0, b1);
                }
            }
        }
        __syncthreads();   // all compute done; zbuf (alias of stage 0) now safe

        // Scatter partials: zbuf[warp_k][n][c]
        {
            const int r4 = lane >> 2;
            const int c2 = (lane & 3) * 2;
            const int c = warp_c * 8 + c2;
#pragma unroll
            for (int mt = 0; mt < 2; mt++) {
                int n = warp_m * 32 + mt * 16 + r4;
                zbuf[(warp_k * 64 + n) * 33 + c] = d[mt][0];
                zbuf[(warp_k * 64 + n) * 33 + c + 1] = d[mt][1];
                zbuf[(warp_k * 64 + n + 8) * 33 + c] = d[mt][2];
                zbuf[(warp_k * 64 + n + 8) * 33 + c + 1] = d[mt][3];
            }
        }
        __syncthreads();

        // Gate epilogue: 1 fixed (n, j) output per thread; c in register
        {
            const int n = e_n, col = J0 + e_j;
            float zi = zbuf[n * 33 + e_j +  0] + zbuf[(64 + n) * 33 + e_j +  0] + x0;
            float zf = zbuf[n * 33 + e_j +  8] + zbuf[(64 + n) * 33 + e_j +  8] + x1;
            float zo = zbuf[n * 33 + e_j + 16] + zbuf[(64 + n) * 33 + e_j + 16] + x2;
            float zg = zbuf[n * 33 + e_j + 24] + zbuf[(64 + n) * 33 + e_j + 24] + x3;

            float iv = fsig(zi);
            float fv = fsig(zf);
            float ov = fsig(zo);
            float gv = ftanh(zg);

            float cn = fv * creg + iv * gv;
            creg = cn;
            float hn = ov * ftanh(cn);

            int hidx = n * HH + col;
            __nv_bfloat16 hi = __float2bfloat16(hn);
            g_hh[par ^ 1][hidx] = hi;
            g_hl[par ^ 1][hidx] = __float2bfloat16(hn - __bfloat162float(hi));
            out[((size_t)n * TT + t) * HH + col] = hn;
        }

        // Grid-wide barrier v2 (slot arrivals + block-0 aggregation)
        if (t + 1 < TT) {
            const unsigned target = (unsigned)(t + 1);
            __syncthreads();                    // all h writes issued
            if (tid == 0) {
                __threadfence();                // order h writes before arrival
                st_release(&g_arrive[blk], target);
            }
            if (blk == 0) {
                if (tid < 128) spin_until(&g_arrive[tid], target);
                __syncthreads();
                if (tid == 0) st_release(&g_phase, target);
            }
            if (tid == 0) spin_until(&g_phase, target);
            __syncthreads();
        }
    }
}

// ---------------------------------------------------------------------------
// Launcher (graph-capturable: kernel launches only)
// ---------------------------------------------------------------------------
extern "C" void kernel_launch(void* const* d_in, const int* in_sizes, int n_in,
                              void* d_out, int out_size) {
    const float* x  = (const float*)d_in[0];
    const float* h0 = (const float*)d_in[1];
    const float* Wx = (const float*)d_in[2];
    const float* Wh = (const float*)d_in[3];
    const float* b  = (const float*)d_in[4];
    float* out = (float*)d_out;

    static int attr_set = 0;
    if (!attr_set) {
        cudaFuncSetAttribute(lstm_persistent,
                             cudaFuncAttributeMaxDynamicSharedMemorySize, P_SMEM);
        cudaFuncSetAttribute(gemm1_mma,
                             cudaFuncAttributeMaxDynamicSharedMemorySize, G1_SMEM);
        attr_set = 1;
    }

    init_kernel<<<(NB * HH + 255) / 256, 256>>>(h0);
    split_wh_kernel<<<(DD * FH + 255) / 256, 256>>>(Wh);
    split_wx_kernel<<<(DD * FH + 255) / 256, 256>>>(Wx);
    split_x_kernel<<<((size_t)MM * DD + 511) / 512, 512>>>(x);

    dim3 g1(FH / 128, MM / 128);   // (32, 256)
    gemm1_mma<<<g1, 256, G1_SMEM>>>(b);

    lstm_persistent<<<128, 512, P_SMEM>>>(out);
}

// round 13
// speedup vs baseline: 1.5966x; 1.3559x over previous
#include <cuda_runtime.h>
#include <cuda_bf16.h>
#include <cuda_fp16.h>
#include <math.h>

#define NB 64
#define TT 512
#define DD 1024
#define HH 1024
#define FH 4096   // 4*H
#define MM 32768  // NB*TT

typedef unsigned long long ull;

// Scratch (device globals — no runtime allocation allowed)
__device__ float g_xz[(size_t)TT * NB * FH];              // (t, n, 4H) : 512 MB
__device__ __half g_whf[(size_t)2048 * FH];               // Wh fp16: rows 0-1023 hi, 1024-2047 lo*2048 (cols permuted)
__device__ __nv_bfloat16 g_wxstack[(size_t)3072 * FH];    // [Wx_hi; Wx_lo; Wx_hi] (bf16, GEMM1)
__device__ __nv_bfloat16 g_xh[(size_t)MM * DD];           // x hi
__device__ __nv_bfloat16 g_xl[(size_t)MM * DD];           // x lo
__device__ __half g_hf[2][NB * HH];                       // h fp16, double-buffered
// Barrier v2: per-block arrival slots + broadcast phase (monotonic counters)
__device__ unsigned g_arrive[128];
__device__ unsigned g_phase;

// ---- helpers ----------------------------------------------------------------
__device__ __forceinline__ unsigned s2u(const void* p) {
    return (unsigned)__cvta_generic_to_shared(p);
}
__device__ __forceinline__ void cp16(void* s, const void* g) {
    asm volatile("cp.async.cg.shared.global [%0], [%1], 16;" :: "r"(s2u(s)), "l"(g));
}
__device__ __forceinline__ unsigned ld_acquire(const unsigned* p) {
    unsigned v;
    asm volatile("ld.acquire.gpu.u32 %0, [%1];" : "=r"(v) : "l"(p) : "memory");
    return v;
}
__device__ __forceinline__ void st_release(unsigned* p, unsigned v) {
    asm volatile("st.release.gpu.u32 [%0], %1;" :: "l"(p), "r"(v) : "memory");
}
__device__ __forceinline__ void spin_until(const unsigned* p, unsigned target) {
    while (ld_acquire(p) < target) {}
}
// Fast gates (MUFU paths, flag-independent)
__device__ __forceinline__ float fsig(float x) {
    return __fdividef(1.0f, 1.0f + __expf(-x));
}
__device__ __forceinline__ float ftanh(float x) {
    return __fmaf_rn(2.0f, __fdividef(1.0f, 1.0f + __expf(-2.0f * x)), -1.0f);
}
#define LDSM_X4(r0, r1, r2, r3, addr) \
    asm volatile("ldmatrix.sync.aligned.m8n8.x4.shared.b16 {%0,%1,%2,%3}, [%4];" \
                 : "=r"(r0), "=r"(r1), "=r"(r2), "=r"(r3) : "r"(addr))
#define LDSM_X2T(r0, r1, addr) \
    asm volatile("ldmatrix.sync.aligned.m8n8.x2.trans.shared.b16 {%0,%1}, [%2];" \
                 : "=r"(r0), "=r"(r1) : "r"(addr))
#define LDSM_X4T(r0, r1, r2, r3, addr) \
    asm volatile("ldmatrix.sync.aligned.m8n8.x4.trans.shared.b16 {%0,%1,%2,%3}, [%4];" \
                 : "=r"(r0), "=r"(r1), "=r"(r2), "=r"(r3) : "r"(addr))
#define MMA16816BF(d0, d1, d2, d3, a0, a1, a2, a3, b0, b1) \
    asm volatile("mma.sync.aligned.m16n8k16.row.col.f32.bf16.bf16.f32 " \
                 "{%0,%1,%2,%3}, {%4,%5,%6,%7}, {%8,%9}, {%0,%1,%2,%3};" \
                 : "+f"(d0), "+f"(d1), "+f"(d2), "+f"(d3) \
                 : "r"(a0), "r"(a1), "r"(a2), "r"(a3), "r"(b0), "r"(b1))
#define MMA16816F16(d0, d1, d2, d3, a0, a1, a2, a3, b0, b1) \
    asm volatile("mma.sync.aligned.m16n8k16.row.col.f32.f16.f16.f32 " \
                 "{%0,%1,%2,%3}, {%4,%5,%6,%7}, {%8,%9}, {%0,%1,%2,%3};" \
                 : "+f"(d0), "+f"(d1), "+f"(d2), "+f"(d3) \
                 : "r"(a0), "r"(a1), "r"(a2), "r"(a3), "r"(b0), "r"(b1))

// ---------------------------------------------------------------------------
// Init / precompute kernels
// ---------------------------------------------------------------------------
__global__ void init_kernel(const float* __restrict__ h0) {
    int i = blockIdx.x * blockDim.x + threadIdx.x;
    if (i < 128) g_arrive[i] = 0;
    if (i == 128) g_phase = 0;
    if (i < NB * HH) {
        g_hf[0][i] = __float2half_rn(h0[i]);
    }
}

// Wh fp16 split + block-column permute: col_new = blk*32 + g*8 + j
// lo stored scaled by 2048 to stay in fp16 normal range.
__global__ void split_wh_kernel(const float* __restrict__ Wh) {
    int i = blockIdx.x * blockDim.x + threadIdx.x;
    if (i >= DD * FH) return;
    int k = i >> 12;
    int co = i & 4095;
    float w = Wh[i];
    __half hi = __float2half_rn(w);
    float lo = (w - __half2float(hi)) * 2048.0f;
    int g = co >> 10;
    int within = co & 1023;
    int blk = within >> 3;
    int j = within & 7;
    size_t col = (size_t)blk * 32 + g * 8 + j;
    g_whf[(size_t)k * FH + col] = hi;
    g_whf[(size_t)(k + 1024) * FH + col] = __float2half_rn(lo);
}

// Wx split stacked (bf16, for GEMM1): rows [0,1024): hi, [1024,2048): lo, [2048,3072): hi
__global__ void split_wx_kernel(const float* __restrict__ Wx) {
    int i = blockIdx.x * blockDim.x + threadIdx.x;
    if (i >= DD * FH) return;
    int k = i >> 12;
    int co = i & 4095;
    float w = Wx[i];
    __nv_bfloat16 hi = __float2bfloat16(w);
    __nv_bfloat16 lo = __float2bfloat16(w - __bfloat162float(hi));
    g_wxstack[(size_t)k * FH + co] = hi;
    g_wxstack[(size_t)(k + 1024) * FH + co] = lo;
    g_wxstack[(size_t)(k + 2048) * FH + co] = hi;
}

__global__ void split_x_kernel(const float* __restrict__ X) {
    size_t i = (size_t)blockIdx.x * blockDim.x + threadIdx.x;
    if (i >= (size_t)MM * DD) return;
    float v = X[i];
    __nv_bfloat16 hi = __float2bfloat16(v);
    g_xh[i] = hi;
    g_xl[i] = __float2bfloat16(v - __bfloat162float(hi));
}

// ---------------------------------------------------------------------------
// GEMM1 (split-bf16 MMA, unchanged; L2-bound ~1.3 ms)
// ---------------------------------------------------------------------------
#define G1_ASTR 40
#define G1_BSTR 136
#define G1_ABYTES (128 * G1_ASTR * 2)
#define G1_BBYTES (32 * G1_BSTR * 2)
#define G1_STAGE  (G1_ABYTES + G1_BBYTES)
#define G1_SMEM   (3 * G1_STAGE)
#define G1_NSLAB  96

__global__ __launch_bounds__(256) void gemm1_mma(const float* __restrict__ b) {
    extern __shared__ __align__(16) char sm1[];

    const int tid = threadIdx.x;
    const int lane = tid & 31;
    const int wid = tid >> 5;
    const int warp_m = wid >> 1;
    const int warp_n = wid & 1;
    const int m0 = blockIdx.y * 128;
    const int n0 = blockIdx.x * 128;

    const int lr = lane & 7;
    const int lg = lane >> 3;
    const int a_row_off = ((lg & 1) << 3) + lr;
    const int a_k_off = (lg >> 1) << 3;
    const int bt_row = lr + ((lg & 1) << 3);
    const int bt_c8 = (lane >> 4) << 3;

    float d[2][8][4];
#pragma unroll
    for (int mt = 0; mt < 2; mt++)
#pragma unroll
        for (int nt = 0; nt < 8; nt++)
#pragma unroll
            for (int r = 0; r < 4; r++) d[mt][nt][r] = 0.0f;

    auto prefetch = [&](int sp) {
        char* stg = sm1 + (sp % 3) * G1_STAGE;
        __nv_bfloat16* As = (__nv_bfloat16*)stg;
        __nv_bfloat16* Bs = (__nv_bfloat16*)(stg + G1_ABYTES);
        const __nv_bfloat16* asrc = (sp < 64) ? g_xh : g_xl;
        const int kin = (sp * 32) & 1023;
#pragma unroll
        for (int i = 0; i < 2; i++) {
            int idx = tid + i * 256;
            int row = idx >> 2, ch = idx & 3;
            cp16(&As[row * G1_ASTR + ch * 8],
                 &asrc[(size_t)(m0 + row) * DD + kin + ch * 8]);
        }
#pragma unroll
        for (int i = 0; i < 2; i++) {
            int idx = tid + i * 256;
            int row = idx >> 4, ch = idx & 15;
            cp16(&Bs[row * G1_BSTR + ch * 8],
                 &g_wxstack[(size_t)(sp * 32 + row) * FH + n0 + ch * 8]);
        }
        asm volatile("cp.async.commit_group;");
    };

    prefetch(0);
    prefetch(1);

    for (int s = 0; s < G1_NSLAB; s++) {
        asm volatile("cp.async.wait_group 1;");
        __syncthreads();
        if (s + 2 < G1_NSLAB) prefetch(s + 2);
        else asm volatile("cp.async.commit_group;");

        char* stg = sm1 + (s % 3) * G1_STAGE;
        const __nv_bfloat16* As = (const __nv_bfloat16*)stg;
        const __nv_bfloat16* Bs = (const __nv_bfloat16*)(stg + G1_ABYTES);

#pragma unroll
        for (int ks = 0; ks < 2; ks++) {
            const int kk0 = ks * 16;
            unsigned a[2][4];
#pragma unroll
            for (int mt = 0; mt < 2; mt++) {
                unsigned addr = s2u(&As[(warp_m * 32 + mt * 16 + a_row_off) * G1_ASTR
                                        + kk0 + a_k_off]);
                LDSM_X4(a[mt][0], a[mt][1], a[mt][2], a[mt][3], addr);
            }
            unsigned bf[4][4];
#pragma unroll
            for (int np = 0; np < 4; np++) {
                unsigned addr = s2u(&Bs[(kk0 + bt_row) * G1_BSTR
                                        + warp_n * 64 + np * 16 + bt_c8]);
                LDSM_X4T(bf[np][0], bf[np][1], bf[np][2], bf[np][3], addr);
            }
#pragma unroll
            for (int mt = 0; mt < 2; mt++)
#pragma unroll
                for (int nt = 0; nt < 8; nt++) {
                    unsigned b0 = bf[nt >> 1][(nt & 1) * 2 + 0];
                    unsigned b1 = bf[nt >> 1][(nt & 1) * 2 + 1];
                    MMA16816BF(d[mt][nt][0], d[mt][nt][1], d[mt][nt][2], d[mt][nt][3],
                               a[mt][0], a[mt][1], a[mt][2], a[mt][3], b0, b1);
                }
        }
    }

    const int r4 = lane >> 2;
    const int c2 = (lane & 3) * 2;
#pragma unroll
    for (int mt = 0; mt < 2; mt++) {
        int mbase = m0 + warp_m * 32 + mt * 16;
#pragma unroll
        for (int nt = 0; nt < 8; nt++) {
            int col = n0 + warp_n * 64 + nt * 8 + c2;
            float b0 = b[col], b1 = b[col + 1];
            int m = mbase + r4;
            int nb = m >> 9, tl = m & 511;
            float2 v0 = {d[mt][nt][0] + b0, d[mt][nt][1] + b1};
            *(float2*)&g_xz[(size_t)(tl * NB + nb) * FH + col] = v0;
            m += 8; nb = m >> 9; tl = m & 511;
            float2 v1 = {d[mt][nt][2] + b0, d[mt][nt][3] + b1};
            *(float2*)&g_xz[(size_t)(tl * NB + nb) * FH + col] = v1;
        }
    }
}

// ---------------------------------------------------------------------------
// Persistent recurrence kernel — fp16 2-product scheme.
// 128 blocks x 512 threads (16 warps: 2k x 2m x 4c). W (fp16 hi + scaled lo)
// resident in SMEM; h (single fp16 buffer) in 4 slabs of 256k, double-buffered.
// z = h*W_hi + (h*W_lo')/2048.
// ---------------------------------------------------------------------------
#define WS_STR 40    // fp16; 80 B rows
#define HS_STR 264   // fp16; 528 B rows (odd multiple of 16B)
#define KSLAB 256
#define HS_STAGE_B (64 * HS_STR * 2)                 // 33792
#define SMEM_WS_B (2048 * WS_STR * 2)                // 163840
#define P_SMEM (SMEM_WS_B + 2 * HS_STAGE_B)          // 231424

__global__ __launch_bounds__(512, 1) void lstm_persistent(float* __restrict__ out) {
    extern __shared__ __align__(16) char smp[];
    __half* ws = (__half*)smp;                        // [2048][WS_STR]
    __half* hsm = (__half*)(smp + SMEM_WS_B);         // 2 stages
    float* zbuf = (float*)(smp + SMEM_WS_B);          // alias of stage 0: [2][64][33]

    const int tid = threadIdx.x;
    const int lane = tid & 31;
    const int wid = tid >> 5;
    const int warp_k = wid >> 3;        // 0..1
    const int warp_m = (wid >> 2) & 1;  // 0..1
    const int warp_c = wid & 3;         // 0..3
    const int blk = blockIdx.x;

    // --- Load this block's W slice into SMEM (once) ---
    {
        const __half* wsrc = g_whf + (size_t)blk * 32;
#pragma unroll
        for (int i = 0; i < 16; i++) {
            int c = tid + i * 512;
            int row = c >> 2, q = c & 3;
            *(uint4*)&ws[row * WS_STR + q * 8] =
                *(const uint4*)&wsrc[(size_t)row * FH + q * 8];
        }
    }
    __syncthreads();

    // ldmatrix lane addressing
    const int lr = lane & 7;
    const int lg = lane >> 3;
    const int a_row_off = ((lg & 1) << 3) + lr;
    const int a_k_off = (lg >> 1) << 3;
    const int b_krow = lane & 15;

    // epilogue mapping: 1 output per thread
    const int e_n = tid >> 3;
    const int e_j = tid & 7;
    const int J0 = blk * 8;
    float creg = 0.0f;

    for (int t = 0; t < TT; t++) {
        const int par = t & 1;
        const __half* __restrict__ hf = g_hf[par];

        // Early xz prefetch (DRAM latency hidden behind the slab loop)
        const float* xr = g_xz + (size_t)(t * NB + e_n) * FH + J0 + e_j;
        float x0 = __ldg(xr);
        float x1 = __ldg(xr + 1024);
        float x2 = __ldg(xr + 2048);
        float x3 = __ldg(xr + 3072);

        float d[2][4], dlo[2][4];
#pragma unroll
        for (int mt = 0; mt < 2; mt++)
#pragma unroll
            for (int r = 0; r < 4; r++) { d[mt][r] = 0.0f; dlo[mt][r] = 0.0f; }

        // 4 slabs of 256 k each
        auto pf = [&](int s) {
            const int hk = s * KSLAB;
            __half* dst = hsm + (s & 1) * 64 * HS_STR;
#pragma unroll
            for (int i = 0; i < 4; i++) {
                int idx = tid + i * 512;    // 2048 chunks of 16B
                int n = idx >> 5, ch = idx & 31;
                cp16(&dst[n * HS_STR + ch * 8], &hf[n * HH + hk + ch * 8]);
            }
            asm volatile("cp.async.commit_group;");
        };

        pf(0);

        for (int s = 0; s < 4; s++) {
            asm volatile("cp.async.wait_group 0;");
            __syncthreads();
            if (s + 1 < 4) pf(s + 1);

            const __half* hbuf = hsm + (s & 1) * 64 * HS_STR;
            const int kw = s * KSLAB;

#pragma unroll
            for (int ks = 0; ks < 8; ks++) {
                const int kk0 = warp_k * 128 + ks * 16;
                unsigned a[2][4];
#pragma unroll
                for (int mt = 0; mt < 2; mt++) {
                    unsigned addr = s2u(&hbuf[(warp_m * 32 + mt * 16 + a_row_off) * HS_STR
                                              + kk0 + a_k_off]);
                    LDSM_X4(a[mt][0], a[mt][1], a[mt][2], a[mt][3], addr);
                }
                {   // W_hi product
                    unsigned b0, b1;
                    unsigned addr = s2u(&ws[(kw + kk0 + b_krow) * WS_STR + warp_c * 8]);
                    LDSM_X2T(b0, b1, addr);
#pragma unroll
                    for (int mt = 0; mt < 2; mt++)
                        MMA16816F16(d[mt][0], d[mt][1], d[mt][2], d[mt][3],
                                    a[mt][0], a[mt][1], a[mt][2], a[mt][3], b0, b1);
                }
                {   // W_lo' product (scaled by 2048)
                    unsigned b0, b1;
                    unsigned addr = s2u(&ws[(1024 + kw + kk0 + b_krow) * WS_STR + warp_c * 8]);
                    LDSM_X2T(b0, b1, addr);
#pragma unroll
                    for (int mt = 0; mt < 2; mt++)
                        MMA16816F16(dlo[mt][0], dlo[mt][1], dlo[mt][2], dlo[mt][3],
                                    a[mt][0], a[mt][1], a[mt][2], a[mt][3], b0, b1);
                }
            }
        }
        __syncthreads();   // all compute done; zbuf (alias of stage 0) now safe

        // Scatter partials (combine lo with 1/2048 scale): zbuf[warp_k][n][c]
        {
            const float ls = 1.0f / 2048.0f;
            const int r4 = lane >> 2;
            const int c2 = (lane & 3) * 2;
            const int c = warp_c * 8 + c2;
#pragma unroll
            for (int mt = 0; mt < 2; mt++) {
                int n = warp_m * 32 + mt * 16 + r4;
                zbuf[(warp_k * 64 + n) * 33 + c]     = __fmaf_rn(dlo[mt][0], ls, d[mt][0]);
                zbuf[(warp_k * 64 + n) * 33 + c + 1] = __fmaf_rn(dlo[mt][1], ls, d[mt][1]);
                zbuf[(warp_k * 64 + n + 8) * 33 + c]     = __fmaf_rn(dlo[mt][2], ls, d[mt][2]);
                zbuf[(warp_k * 64 + n + 8) * 33 + c + 1] = __fmaf_rn(dlo[mt][3], ls, d[mt][3]);
            }
        }
        __syncthreads();

        // Gate epilogue: 1 fixed (n, j) output per thread; c in register
        {
            const int n = e_n, col = J0 + e_j;
            float zi = zbuf[n * 33 + e_j +  0] + zbuf[(64 + n) * 33 + e_j +  0] + x0;
            float zf = zbuf[n * 33 + e_j +  8] + zbuf[(64 + n) * 33 + e_j +  8] + x1;
            float zo = zbuf[n * 33 + e_j + 16] + zbuf[(64 + n) * 33 + e_j + 16] + x2;
            float zg = zbuf[n * 33 + e_j + 24] + zbuf[(64 + n) * 33 + e_j + 24] + x3;

            float iv = fsig(zi);
            float fv = fsig(zf);
            float ov = fsig(zo);
            float gv = ftanh(zg);

            float cn = fv * creg + iv * gv;
            creg = cn;
            float hn = ov * ftanh(cn);

            int hidx = n * HH + col;
            g_hf[par ^ 1][hidx] = __float2half_rn(hn);
            out[((size_t)n * TT + t) * HH + col] = hn;
        }

        // Grid-wide barrier v2 (slot arrivals + block-0 aggregation)
        if (t + 1 < TT) {
            const unsigned target = (unsigned)(t + 1);
            __syncthreads();                    // all h writes issued
            if (tid == 0) {
                __threadfence();                // order h writes before arrival
                st_release(&g_arrive[blk], target);
            }
            if (blk == 0) {
                if (tid < 128) spin_until(&g_arrive[tid], target);
                __syncthreads();
                if (tid == 0) st_release(&g_phase, target);
            }
            if (tid == 0) spin_until(&g_phase, target);
            __syncthreads();
        }
    }
}

// ---------------------------------------------------------------------------
// Launcher (graph-capturable: kernel launches only)
// ---------------------------------------------------------------------------
extern "C" void kernel_launch(void* const* d_in, const int* in_sizes, int n_in,
                              void* d_out, int out_size) {
    const float* x  = (const float*)d_in[0];
    const float* h0 = (const float*)d_in[1];
    const float* Wx = (const float*)d_in[2];
    const float* Wh = (const float*)d_in[3];
    const float* b  = (const float*)d_in[4];
    float* out = (float*)d_out;

    static int attr_set = 0;
    if (!attr_set) {
        cudaFuncSetAttribute(lstm_persistent,
                             cudaFuncAttributeMaxDynamicSharedMemorySize, P_SMEM);
        cudaFuncSetAttribute(gemm1_mma,
                             cudaFuncAttributeMaxDynamicSharedMemorySize, G1_SMEM);
        attr_set = 1;
    }

    init_kernel<<<(NB * HH + 255) / 256, 256>>>(h0);
    split_wh_kernel<<<(DD * FH + 255) / 256, 256>>>(Wh);
    split_wx_kernel<<<(DD * FH + 255) / 256, 256>>>(Wx);
    split_x_kernel<<<((size_t)MM * DD + 511) / 512, 512>>>(x);

    dim3 g1(FH / 128, MM / 128);   // (32, 256)
    gemm1_mma<<<g1, 256, G1_SMEM>>>(b);

    lstm_persistent<<<128, 512, P_SMEM>>>(out);
}

// round 14
// speedup vs baseline: 1.9601x; 1.2277x over previous
#include <cuda_runtime.h>
#include <cuda_fp16.h>
#include <math.h>

#define NB 64
#define TT 512
#define DD 1024
#define HH 1024
#define FH 4096   // 4*H
#define MM 32768  // NB*TT

typedef unsigned long long ull;

// Scratch (device globals — no runtime allocation allowed)
__device__ float g_xz[(size_t)TT * NB * FH];        // (t, n, 4H) : 512 MB
__device__ __half g_whf[(size_t)1024 * FH];         // Wh fp16 hi only (cols permuted)
__device__ __half g_wxf[(size_t)2048 * FH];         // Wx fp16: rows 0-1023 lo*2048, 1024-2047 hi
__device__ __half g_xf[(size_t)MM * DD];            // x fp16
__device__ __half g_hf[2][NB * HH];                 // h fp16, double-buffered
// Barrier v2: per-block arrival slots + broadcast phase (monotonic counters)
__device__ unsigned g_arrive[128];
__device__ unsigned g_phase;

// ---- helpers ----------------------------------------------------------------
__device__ __forceinline__ unsigned s2u(const void* p) {
    return (unsigned)__cvta_generic_to_shared(p);
}
__device__ __forceinline__ void cp16(void* s, const void* g) {
    asm volatile("cp.async.cg.shared.global [%0], [%1], 16;" :: "r"(s2u(s)), "l"(g));
}
__device__ __forceinline__ unsigned ld_acquire(const unsigned* p) {
    unsigned v;
    asm volatile("ld.acquire.gpu.u32 %0, [%1];" : "=r"(v) : "l"(p) : "memory");
    return v;
}
__device__ __forceinline__ void st_release(unsigned* p, unsigned v) {
    asm volatile("st.release.gpu.u32 [%0], %1;" :: "l"(p), "r"(v) : "memory");
}
__device__ __forceinline__ void spin_until(const unsigned* p, unsigned target) {
    while (ld_acquire(p) < target) {}
}
// Fast gates (MUFU paths, flag-independent)
__device__ __forceinline__ float fsig(float x) {
    return __fdividef(1.0f, 1.0f + __expf(-x));
}
__device__ __forceinline__ float ftanh(float x) {
    return __fmaf_rn(2.0f, __fdividef(1.0f, 1.0f + __expf(-2.0f * x)), -1.0f);
}
#define LDSM_X4(r0, r1, r2, r3, addr) \
    asm volatile("ldmatrix.sync.aligned.m8n8.x4.shared.b16 {%0,%1,%2,%3}, [%4];" \
                 : "=r"(r0), "=r"(r1), "=r"(r2), "=r"(r3) : "r"(addr))
#define LDSM_X2T(r0, r1, addr) \
    asm volatile("ldmatrix.sync.aligned.m8n8.x2.trans.shared.b16 {%0,%1}, [%2];" \
                 : "=r"(r0), "=r"(r1) : "r"(addr))
#define LDSM_X4T(r0, r1, r2, r3, addr) \
    asm volatile("ldmatrix.sync.aligned.m8n8.x4.trans.shared.b16 {%0,%1,%2,%3}, [%4];" \
                 : "=r"(r0), "=r"(r1), "=r"(r2), "=r"(r3) : "r"(addr))
#define MMA16816F16(d0, d1, d2, d3, a0, a1, a2, a3, b0, b1) \
    asm volatile("mma.sync.aligned.m16n8k16.row.col.f32.f16.f16.f32 " \
                 "{%0,%1,%2,%3}, {%4,%5,%6,%7}, {%8,%9}, {%0,%1,%2,%3};" \
                 : "+f"(d0), "+f"(d1), "+f"(d2), "+f"(d3) \
                 : "r"(a0), "r"(a1), "r"(a2), "r"(a3), "r"(b0), "r"(b1))

// ---------------------------------------------------------------------------
// Init / precompute kernels
// ---------------------------------------------------------------------------
__global__ void init_kernel(const float* __restrict__ h0) {
    int i = blockIdx.x * blockDim.x + threadIdx.x;
    if (i < 128) g_arrive[i] = 0;
    if (i == 128) g_phase = 0;
    if (i < NB * HH) {
        g_hf[0][i] = __float2half_rn(h0[i]);
    }
}

// Wh fp16 (hi only) + block-column permute: col_new = blk*32 + g*8 + j
__global__ void split_wh_kernel(const float* __restrict__ Wh) {
    int i = blockIdx.x * blockDim.x + threadIdx.x;
    if (i >= DD * FH) return;
    int k = i >> 12;
    int co = i & 4095;
    int g = co >> 10;
    int within = co & 1023;
    int blk = within >> 3;
    int j = within & 7;
    size_t col = (size_t)blk * 32 + g * 8 + j;
    g_whf[(size_t)k * FH + col] = __float2half_rn(Wh[i]);
}

// Wx fp16 split: rows [0,1024) = lo*2048 (processed FIRST, scaled at midpoint),
// rows [1024,2048) = hi
__global__ void split_wx_kernel(const float* __restrict__ Wx) {
    int i = blockIdx.x * blockDim.x + threadIdx.x;
    if (i >= DD * FH) return;
    int k = i >> 12;
    int co = i & 4095;
    float w = Wx[i];
    __half hi = __float2half_rn(w);
    float lo = (w - __half2float(hi)) * 2048.0f;
    g_wxf[(size_t)k * FH + co] = __float2half_rn(lo);
    g_wxf[(size_t)(k + 1024) * FH + co] = hi;
}

__global__ void split_x_kernel(const float* __restrict__ X) {
    size_t i = (size_t)blockIdx.x * blockDim.x + threadIdx.x;
    if (i >= (size_t)MM * DD) return;
    g_xf[i] = __float2half_rn(X[i]);
}

// ---------------------------------------------------------------------------
// GEMM1 (fp16 2-product): xz = x @ (Wx_lo'/2048 + Wx_hi) + b.
// K-stacked 2048: slabs 0-31 = lo' region (d scaled by 1/2048 at s==32),
// slabs 32-63 = hi region. 128x128x32 tiles, 256 threads, 3-stage cp.async.
// ---------------------------------------------------------------------------
#define G1_ASTR 40
#define G1_BSTR 136
#define G1_ABYTES (128 * G1_ASTR * 2)
#define G1_BBYTES (32 * G1_BSTR * 2)
#define G1_STAGE  (G1_ABYTES + G1_BBYTES)
#define G1_SMEM   (3 * G1_STAGE)
#define G1_NSLAB  64

__global__ __launch_bounds__(256) void gemm1_mma(const float* __restrict__ b) {
    extern __shared__ __align__(16) char sm1[];

    const int tid = threadIdx.x;
    const int lane = tid & 31;
    const int wid = tid >> 5;
    const int warp_m = wid >> 1;
    const int warp_n = wid & 1;
    const int m0 = blockIdx.y * 128;
    const int n0 = blockIdx.x * 128;

    const int lr = lane & 7;
    const int lg = lane >> 3;
    const int a_row_off = ((lg & 1) << 3) + lr;
    const int a_k_off = (lg >> 1) << 3;
    const int bt_row = lr + ((lg & 1) << 3);
    const int bt_c8 = (lane >> 4) << 3;

    float d[2][8][4];
#pragma unroll
    for (int mt = 0; mt < 2; mt++)
#pragma unroll
        for (int nt = 0; nt < 8; nt++)
#pragma unroll
            for (int r = 0; r < 4; r++) d[mt][nt][r] = 0.0f;

    auto prefetch = [&](int sp) {
        char* stg = sm1 + (sp % 3) * G1_STAGE;
        __half* As = (__half*)stg;
        __half* Bs = (__half*)(stg + G1_ABYTES);
        const int kin = (sp * 32) & 1023;
#pragma unroll
        for (int i = 0; i < 2; i++) {
            int idx = tid + i * 256;
            int row = idx >> 2, ch = idx & 3;
            cp16(&As[row * G1_ASTR + ch * 8],
                 &g_xf[(size_t)(m0 + row) * DD + kin + ch * 8]);
        }
#pragma unroll
        for (int i = 0; i < 2; i++) {
            int idx = tid + i * 256;
            int row = idx >> 4, ch = idx & 15;
            cp16(&Bs[row * G1_BSTR + ch * 8],
                 &g_wxf[(size_t)(sp * 32 + row) * FH + n0 + ch * 8]);
        }
        asm volatile("cp.async.commit_group;");
    };

    prefetch(0);
    prefetch(1);

    for (int s = 0; s < G1_NSLAB; s++) {
        asm volatile("cp.async.wait_group 1;");
        __syncthreads();
        if (s + 2 < G1_NSLAB) prefetch(s + 2);
        else asm volatile("cp.async.commit_group;");

        // Midpoint: lo' region fully accumulated -> scale down once
        if (s == 32) {
            const float ls = 1.0f / 2048.0f;
#pragma unroll
            for (int mt = 0; mt < 2; mt++)
#pragma unroll
                for (int nt = 0; nt < 8; nt++)
#pragma unroll
                    for (int r = 0; r < 4; r++) d[mt][nt][r] *= ls;
        }

        char* stg = sm1 + (s % 3) * G1_STAGE;
        const __half* As = (const __half*)stg;
        const __half* Bs = (const __half*)(stg + G1_ABYTES);

#pragma unroll
        for (int ks = 0; ks < 2; ks++) {
            const int kk0 = ks * 16;
            unsigned a[2][4];
#pragma unroll
            for (int mt = 0; mt < 2; mt++) {
                unsigned addr = s2u(&As[(warp_m * 32 + mt * 16 + a_row_off) * G1_ASTR
                                        + kk0 + a_k_off]);
                LDSM_X4(a[mt][0], a[mt][1], a[mt][2], a[mt][3], addr);
            }
            unsigned bf[4][4];
#pragma unroll
            for (int np = 0; np < 4; np++) {
                unsigned addr = s2u(&Bs[(kk0 + bt_row) * G1_BSTR
                                        + warp_n * 64 + np * 16 + bt_c8]);
                LDSM_X4T(bf[np][0], bf[np][1], bf[np][2], bf[np][3], addr);
            }
#pragma unroll
            for (int mt = 0; mt < 2; mt++)
#pragma unroll
                for (int nt = 0; nt < 8; nt++) {
                    unsigned b0 = bf[nt >> 1][(nt & 1) * 2 + 0];
                    unsigned b1 = bf[nt >> 1][(nt & 1) * 2 + 1];
                    MMA16816F16(d[mt][nt][0], d[mt][nt][1], d[mt][nt][2], d[mt][nt][3],
                                a[mt][0], a[mt][1], a[mt][2], a[mt][3], b0, b1);
                }
        }
    }

    const int r4 = lane >> 2;
    const int c2 = (lane & 3) * 2;
#pragma unroll
    for (int mt = 0; mt < 2; mt++) {
        int mbase = m0 + warp_m * 32 + mt * 16;
#pragma unroll
        for (int nt = 0; nt < 8; nt++) {
            int col = n0 + warp_n * 64 + nt * 8 + c2;
            float b0 = b[col], b1 = b[col + 1];
            int m = mbase + r4;
            int nb = m >> 9, tl = m & 511;
            float2 v0 = {d[mt][nt][0] + b0, d[mt][nt][1] + b1};
            *(float2*)&g_xz[(size_t)(tl * NB + nb) * FH + col] = v0;
            m += 8; nb = m >> 9; tl = m & 511;
            float2 v1 = {d[mt][nt][2] + b0, d[mt][nt][3] + b1};
            *(float2*)&g_xz[(size_t)(tl * NB + nb) * FH + col] = v1;
        }
    }
}

// ---------------------------------------------------------------------------
// Persistent recurrence kernel — fp16 single-product.
// 128 blocks x 512 threads (16 warps: 2k x 2m x 4c). W_hi (fp16, 80 KB)
// resident in SMEM; h (fp16, 128 KB) staged per step in 4 slabs, ALL issued
// at step start (staged wait_group 3/2/1/0). z = h * W_hi.
// ---------------------------------------------------------------------------
#define WS_STR 40    // fp16; 80 B rows
#define HS_STR 264   // fp16; 528 B rows (odd multiple of 16B)
#define KSLAB 256
#define HS_STAGE_B (64 * HS_STR * 2)                 // 33792
#define SMEM_WS_B (1024 * WS_STR * 2)                // 81920
#define P_SMEM (SMEM_WS_B + 4 * HS_STAGE_B)          // 217088

__global__ __launch_bounds__(512, 1) void lstm_persistent(float* __restrict__ out) {
    extern __shared__ __align__(16) char smp[];
    __half* ws = (__half*)smp;                        // [1024][WS_STR]
    __half* hsm = (__half*)(smp + SMEM_WS_B);         // 4 stages
    float* zbuf = (float*)(smp + SMEM_WS_B);          // alias of stages 0-1: [2][64][33]

    const int tid = threadIdx.x;
    const int lane = tid & 31;
    const int wid = tid >> 5;
    const int warp_k = wid >> 3;        // 0..1
    const int warp_m = (wid >> 2) & 1;  // 0..1
    const int warp_c = wid & 3;         // 0..3
    const int blk = blockIdx.x;

    // --- Load this block's W slice into SMEM (once) ---
    {
        const __half* wsrc = g_whf + (size_t)blk * 32;
#pragma unroll
        for (int i = 0; i < 8; i++) {
            int c = tid + i * 512;          // 0..4095 16B-chunks
            int row = c >> 2, q = c & 3;
            *(uint4*)&ws[row * WS_STR + q * 8] =
                *(const uint4*)&wsrc[(size_t)row * FH + q * 8];
        }
    }
    __syncthreads();

    // ldmatrix lane addressing
    const int lr = lane & 7;
    const int lg = lane >> 3;
    const int a_row_off = ((lg & 1) << 3) + lr;
    const int a_k_off = (lg >> 1) << 3;
    const int b_krow = lane & 15;

    // epilogue mapping: 1 output per thread
    const int e_n = tid >> 3;
    const int e_j = tid & 7;
    const int J0 = blk * 8;
    float creg = 0.0f;

    for (int t = 0; t < TT; t++) {
        const int par = t & 1;
        const __half* __restrict__ hf = g_hf[par];

        // Early xz prefetch (DRAM latency hidden behind the slab loop)
        const float* xr = g_xz + (size_t)(t * NB + e_n) * FH + J0 + e_j;
        float x0 = __ldg(xr);
        float x1 = __ldg(xr + 1024);
        float x2 = __ldg(xr + 2048);
        float x3 = __ldg(xr + 3072);

        float d[2][4];
#pragma unroll
        for (int mt = 0; mt < 2; mt++)
#pragma unroll
            for (int r = 0; r < 4; r++) d[mt][r] = 0.0f;

        // Issue ALL 4 slab loads up front (one commit group each)
#pragma unroll
        for (int s = 0; s < 4; s++) {
            const int hk = s * KSLAB;
            __half* dst = hsm + s * 64 * HS_STR;
#pragma unroll
            for (int i = 0; i < 4; i++) {
                int idx = tid + i * 512;    // 2048 chunks of 16B
                int n = idx >> 5, ch = idx & 31;
                cp16(&dst[n * HS_STR + ch * 8], &hf[n * HH + hk + ch * 8]);
            }
            asm volatile("cp.async.commit_group;");
        }

        // Compute slab s after its group lands (wait_group 3-s pending)
#define REC_SLAB(s, wcnt)                                                          \
        {                                                                          \
            asm volatile("cp.async.wait_group %0;" :: "n"(wcnt));                  \
            __syncthreads();                                                       \
            const __half* hbuf = hsm + (s) * 64 * HS_STR;                          \
            const int kw = (s) * KSLAB;                                            \
            _Pragma("unroll")                                                      \
            for (int ks = 0; ks < 8; ks++) {                                       \
                const int kk0 = warp_k * 128 + ks * 16;                            \
                unsigned a[2][4];                                                  \
                _Pragma("unroll")                                                  \
                for (int mt = 0; mt < 2; mt++) {                                   \
                    unsigned addr = s2u(&hbuf[(warp_m * 32 + mt * 16 + a_row_off)  \
                                              * HS_STR + kk0 + a_k_off]);          \
                    LDSM_X4(a[mt][0], a[mt][1], a[mt][2], a[mt][3], addr);         \
                }                                                                  \
                unsigned b0, b1;                                                   \
                unsigned addr = s2u(&ws[(kw + kk0 + b_krow) * WS_STR + warp_c * 8]);\
                LDSM_X2T(b0, b1, addr);                                            \
                _Pragma("unroll")                                                  \
                for (int mt = 0; mt < 2; mt++)                                     \
                    MMA16816F16(d[mt][0], d[mt][1], d[mt][2], d[mt][3],            \
                                a[mt][0], a[mt][1], a[mt][2], a[mt][3], b0, b1);   \
            }                                                                      \
        }

        REC_SLAB(0, 3)
        REC_SLAB(1, 2)
        REC_SLAB(2, 1)
        REC_SLAB(3, 0)
#undef REC_SLAB

        __syncthreads();   // all compute done; zbuf (alias of stages 0-1) now safe

        // Scatter partials: zbuf[warp_k][n][c]
        {
            const int r4 = lane >> 2;
            const int c2 = (lane & 3) * 2;
            const int c = warp_c * 8 + c2;
#pragma unroll
            for (int mt = 0; mt < 2; mt++) {
                int n = warp_m * 32 + mt * 16 + r4;
                zbuf[(warp_k * 64 + n) * 33 + c] = d[mt][0];
                zbuf[(warp_k * 64 + n) * 33 + c + 1] = d[mt][1];
                zbuf[(warp_k * 64 + n + 8) * 33 + c] = d[mt][2];
                zbuf[(warp_k * 64 + n + 8) * 33 + c + 1] = d[mt][3];
            }
        }
        __syncthreads();

        // Gate epilogue: 1 fixed (n, j) output per thread; c in register
        {
            const int n = e_n, col = J0 + e_j;
            float zi = zbuf[n * 33 + e_j +  0] + zbuf[(64 + n) * 33 + e_j +  0] + x0;
            float zf = zbuf[n * 33 + e_j +  8] + zbuf[(64 + n) * 33 + e_j +  8] + x1;
            float zo = zbuf[n * 33 + e_j + 16] + zbuf[(64 + n) * 33 + e_j + 16] + x2;
            float zg = zbuf[n * 33 + e_j + 24] + zbuf[(64 + n) * 33 + e_j + 24] + x3;

            float iv = fsig(zi);
            float fv = fsig(zf);
            float ov = fsig(zo);
            float gv = ftanh(zg);

            float cn = fv * creg + iv * gv;
            creg = cn;
            float hn = ov * ftanh(cn);

            int hidx = n * HH + col;
            g_hf[par ^ 1][hidx] = __float2half_rn(hn);
            out[((size_t)n * TT + t) * HH + col] = hn;
        }

        // Grid-wide barrier v2 (slot arrivals + block-0 aggregation)
        if (t + 1 < TT) {
            const unsigned target = (unsigned)(t + 1);
            __syncthreads();                    // all h writes issued
            if (tid == 0) {
                __threadfence();                // order h writes before arrival
                st_release(&g_arrive[blk], target);
            }
            if (blk == 0) {
                if (tid < 128) spin_until(&g_arrive[tid], target);
                __syncthreads();
                if (tid == 0) st_release(&g_phase, target);
            }
            if (tid == 0) spin_until(&g_phase, target);
            __syncthreads();
        }
    }
}

// ---------------------------------------------------------------------------
// Launcher (graph-capturable: kernel launches only)
// ---------------------------------------------------------------------------
extern "C" void kernel_launch(void* const* d_in, const int* in_sizes, int n_in,
                              void* d_out, int out_size) {
    const float* x  = (const float*)d_in[0];
    const float* h0 = (const float*)d_in[1];
    const float* Wx = (const float*)d_in[2];
    const float* Wh = (const float*)d_in[3];
    const float* b  = (const float*)d_in[4];
    float* out = (float*)d_out;

    static int attr_set = 0;
    if (!attr_set) {
        cudaFuncSetAttribute(lstm_persistent,
                             cudaFuncAttributeMaxDynamicSharedMemorySize, P_SMEM);
        cudaFuncSetAttribute(gemm1_mma,
                             cudaFuncAttributeMaxDynamicSharedMemorySize, G1_SMEM);
        attr_set = 1;
    }

    init_kernel<<<(NB * HH + 255) / 256, 256>>>(h0);
    split_wh_kernel<<<(DD * FH + 255) / 256, 256>>>(Wh);
    split_wx_kernel<<<(DD * FH + 255) / 256, 256>>>(Wx);
    split_x_kernel<<<((size_t)MM * DD + 511) / 512, 512>>>(x);

    dim3 g1(FH / 128, MM / 128);   // (32, 256)
    gemm1_mma<<<g1, 256, G1_SMEM>>>(b);

    lstm_persistent<<<128, 512, P_SMEM>>>(out);
}

// round 15
// speedup vs baseline: 2.3035x; 1.1752x over previous
#include <cuda_runtime.h>
#include <cuda_fp16.h>
#include <math.h>

#define NB 64
#define TT 512
#define DD 1024
#define HH 1024
#define FH 4096   // 4*H
#define MM 32768  // NB*TT

typedef unsigned long long ull;

// Scratch (device globals — no runtime allocation allowed)
__device__ float g_xz[(size_t)TT * NB * FH];        // (t, n, 4H) : 512 MB
__device__ __half g_whf[(size_t)1024 * FH];         // Wh fp16 (cols permuted)
__device__ __half g_wxf[(size_t)1024 * FH];         // Wx fp16
__device__ __half g_xf[(size_t)MM * DD];            // x fp16
__device__ __half g_hf[2][NB * HH];                 // h fp16, double-buffered
// Barrier v2: per-block arrival slots + broadcast phase (monotonic counters)
__device__ unsigned g_arrive[128];
__device__ unsigned g_phase;

// ---- helpers ----------------------------------------------------------------
__device__ __forceinline__ unsigned s2u(const void* p) {
    return (unsigned)__cvta_generic_to_shared(p);
}
__device__ __forceinline__ void cp16(void* s, const void* g) {
    asm volatile("cp.async.cg.shared.global [%0], [%1], 16;" :: "r"(s2u(s)), "l"(g));
}
__device__ __forceinline__ unsigned ld_acquire(const unsigned* p) {
    unsigned v;
    asm volatile("ld.acquire.gpu.u32 %0, [%1];" : "=r"(v) : "l"(p) : "memory");
    return v;
}
__device__ __forceinline__ void st_release(unsigned* p, unsigned v) {
    asm volatile("st.release.gpu.u32 [%0], %1;" :: "l"(p), "r"(v) : "memory");
}
__device__ __forceinline__ void spin_until(const unsigned* p, unsigned target) {
    while (ld_acquire(p) < target) {}
}
// Fast gates (MUFU paths, flag-independent)
__device__ __forceinline__ float fsig(float x) {
    return __fdividef(1.0f, 1.0f + __expf(-x));
}
__device__ __forceinline__ float ftanh(float x) {
    return __fmaf_rn(2.0f, __fdividef(1.0f, 1.0f + __expf(-2.0f * x)), -1.0f);
}
#define LDSM_X4(r0, r1, r2, r3, addr) \
    asm volatile("ldmatrix.sync.aligned.m8n8.x4.shared.b16 {%0,%1,%2,%3}, [%4];" \
                 : "=r"(r0), "=r"(r1), "=r"(r2), "=r"(r3) : "r"(addr))
#define LDSM_X4T(r0, r1, r2, r3, addr) \
    asm volatile("ldmatrix.sync.aligned.m8n8.x4.trans.shared.b16 {%0,%1,%2,%3}, [%4];" \
                 : "=r"(r0), "=r"(r1), "=r"(r2), "=r"(r3) : "r"(addr))
#define MMA16816F16(d0, d1, d2, d3, a0, a1, a2, a3, b0, b1) \
    asm volatile("mma.sync.aligned.m16n8k16.row.col.f32.f16.f16.f32 " \
                 "{%0,%1,%2,%3}, {%4,%5,%6,%7}, {%8,%9}, {%0,%1,%2,%3};" \
                 : "+f"(d0), "+f"(d1), "+f"(d2), "+f"(d3) \
                 : "r"(a0), "r"(a1), "r"(a2), "r"(a3), "r"(b0), "r"(b1))

// ---------------------------------------------------------------------------
// Init / precompute kernels
// ---------------------------------------------------------------------------
__global__ void init_kernel(const float* __restrict__ h0) {
    int i = blockIdx.x * blockDim.x + threadIdx.x;
    if (i < 128) g_arrive[i] = 0;
    if (i == 128) g_phase = 0;
    if (i < NB * HH) {
        g_hf[0][i] = __float2half_rn(h0[i]);
    }
}

// Wh fp16 + block-column permute: col_new = blk*32 + g*8 + j
__global__ void split_wh_kernel(const float* __restrict__ Wh) {
    int i = blockIdx.x * blockDim.x + threadIdx.x;
    if (i >= DD * FH) return;
    int k = i >> 12;
    int co = i & 4095;
    int g = co >> 10;
    int within = co & 1023;
    int blk = within >> 3;
    int j = within & 7;
    size_t col = (size_t)blk * 32 + g * 8 + j;
    g_whf[(size_t)k * FH + col] = __float2half_rn(Wh[i]);
}

// Wx fp16 (single product)
__global__ void split_wx_kernel(const float* __restrict__ Wx) {
    int i = blockIdx.x * blockDim.x + threadIdx.x;
    if (i >= DD * FH) return;
    g_wxf[i] = __float2half_rn(Wx[i]);
}

__global__ void split_x_kernel(const float* __restrict__ X) {
    size_t i = (size_t)blockIdx.x * blockDim.x + threadIdx.x;
    if (i >= (size_t)MM * DD) return;
    g_xf[i] = __float2half_rn(X[i]);
}

// ---------------------------------------------------------------------------
// GEMM1 (fp16 single product): xz = x @ Wx + b, K=1024.
// 128x128x32 tiles, 256 threads, 3-stage cp.async.
// ---------------------------------------------------------------------------
#define G1_ASTR 40
#define G1_BSTR 136
#define G1_ABYTES (128 * G1_ASTR * 2)
#define G1_BBYTES (32 * G1_BSTR * 2)
#define G1_STAGE  (G1_ABYTES + G1_BBYTES)
#define G1_SMEM   (3 * G1_STAGE)
#define G1_NSLAB  32

__global__ __launch_bounds__(256) void gemm1_mma(const float* __restrict__ b) {
    extern __shared__ __align__(16) char sm1[];

    const int tid = threadIdx.x;
    const int lane = tid & 31;
    const int wid = tid >> 5;
    const int warp_m = wid >> 1;
    const int warp_n = wid & 1;
    const int m0 = blockIdx.y * 128;
    const int n0 = blockIdx.x * 128;

    const int lr = lane & 7;
    const int lg = lane >> 3;
    const int a_row_off = ((lg & 1) << 3) + lr;
    const int a_k_off = (lg >> 1) << 3;
    const int bt_row = lr + ((lg & 1) << 3);
    const int bt_c8 = (lane >> 4) << 3;

    float d[2][8][4];
#pragma unroll
    for (int mt = 0; mt < 2; mt++)
#pragma unroll
        for (int nt = 0; nt < 8; nt++)
#pragma unroll
            for (int r = 0; r < 4; r++) d[mt][nt][r] = 0.0f;

    auto prefetch = [&](int sp) {
        char* stg = sm1 + (sp % 3) * G1_STAGE;
        __half* As = (__half*)stg;
        __half* Bs = (__half*)(stg + G1_ABYTES);
        const int kin = sp * 32;
#pragma unroll
        for (int i = 0; i < 2; i++) {
            int idx = tid + i * 256;
            int row = idx >> 2, ch = idx & 3;
            cp16(&As[row * G1_ASTR + ch * 8],
                 &g_xf[(size_t)(m0 + row) * DD + kin + ch * 8]);
        }
#pragma unroll
        for (int i = 0; i < 2; i++) {
            int idx = tid + i * 256;
            int row = idx >> 4, ch = idx & 15;
            cp16(&Bs[row * G1_BSTR + ch * 8],
                 &g_wxf[(size_t)(kin + row) * FH + n0 + ch * 8]);
        }
        asm volatile("cp.async.commit_group;");
    };

    prefetch(0);
    prefetch(1);

    for (int s = 0; s < G1_NSLAB; s++) {
        asm volatile("cp.async.wait_group 1;");
        __syncthreads();
        if (s + 2 < G1_NSLAB) prefetch(s + 2);
        else asm volatile("cp.async.commit_group;");

        char* stg = sm1 + (s % 3) * G1_STAGE;
        const __half* As = (const __half*)stg;
        const __half* Bs = (const __half*)(stg + G1_ABYTES);

#pragma unroll
        for (int ks = 0; ks < 2; ks++) {
            const int kk0 = ks * 16;
            unsigned a[2][4];
#pragma unroll
            for (int mt = 0; mt < 2; mt++) {
                unsigned addr = s2u(&As[(warp_m * 32 + mt * 16 + a_row_off) * G1_ASTR
                                        + kk0 + a_k_off]);
                LDSM_X4(a[mt][0], a[mt][1], a[mt][2], a[mt][3], addr);
            }
            unsigned bf[4][4];
#pragma unroll
            for (int np = 0; np < 4; np++) {
                unsigned addr = s2u(&Bs[(kk0 + bt_row) * G1_BSTR
                                        + warp_n * 64 + np * 16 + bt_c8]);
                LDSM_X4T(bf[np][0], bf[np][1], bf[np][2], bf[np][3], addr);
            }
#pragma unroll
            for (int mt = 0; mt < 2; mt++)
#pragma unroll
                for (int nt = 0; nt < 8; nt++) {
                    unsigned b0 = bf[nt >> 1][(nt & 1) * 2 + 0];
                    unsigned b1 = bf[nt >> 1][(nt & 1) * 2 + 1];
                    MMA16816F16(d[mt][nt][0], d[mt][nt][1], d[mt][nt][2], d[mt][nt][3],
                                a[mt][0], a[mt][1], a[mt][2], a[mt][3], b0, b1);
                }
        }
    }

    const int r4 = lane >> 2;
    const int c2 = (lane & 3) * 2;
#pragma unroll
    for (int mt = 0; mt < 2; mt++) {
        int mbase = m0 + warp_m * 32 + mt * 16;
#pragma unroll
        for (int nt = 0; nt < 8; nt++) {
            int col = n0 + warp_n * 64 + nt * 8 + c2;
            float b0 = b[col], b1 = b[col + 1];
            int m = mbase + r4;
            int nb = m >> 9, tl = m & 511;
            float2 v0 = {d[mt][nt][0] + b0, d[mt][nt][1] + b1};
            *(float2*)&g_xz[(size_t)(tl * NB + nb) * FH + col] = v0;
            m += 8; nb = m >> 9; tl = m & 511;
            float2 v1 = {d[mt][nt][2] + b0, d[mt][nt][3] + b1};
            *(float2*)&g_xz[(size_t)(tl * NB + nb) * FH + col] = v1;
        }
    }
}

// ---------------------------------------------------------------------------
// Persistent recurrence kernel — fp16 single-product, 2k x 4m x 2c warps.
// 128 blocks x 512 threads. W_hi (fp16, 80 KB) resident in SMEM; h (fp16,
// 128 KB) staged per step in 4 slabs, ALL issued at step start. z = h * W.
// Per k16-chunk per warp: 1 LDSM_X4 (A, 16 rows) + 1 LDSM_X4T (B, 16 cols)
// + 2 MMA — 20% fewer issue ops than the 2m x 4c layout.
// ---------------------------------------------------------------------------
#define WS_STR 40    // fp16; 80 B rows
#define HS_STR 264   // fp16; 528 B rows (odd multiple of 16B)
#define KSLAB 256
#define HS_STAGE_B (64 * HS_STR * 2)                 // 33792
#define SMEM_WS_B (1024 * WS_STR * 2)                // 81920
#define P_SMEM (SMEM_WS_B + 4 * HS_STAGE_B)          // 217088

__global__ __launch_bounds__(512, 1) void lstm_persistent(float* __restrict__ out) {
    extern __shared__ __align__(16) char smp[];
    __half* ws = (__half*)smp;                        // [1024][WS_STR]
    __half* hsm = (__half*)(smp + SMEM_WS_B);         // 4 stages
    float* zbuf = (float*)(smp + SMEM_WS_B);          // alias of stages 0-1: [2][64][33]

    const int tid = threadIdx.x;
    const int lane = tid & 31;
    const int wid = tid >> 5;
    const int warp_k = wid >> 3;        // 0..1 (k-half)
    const int warp_m = (wid >> 1) & 3;  // 0..3 (16 rows each)
    const int warp_c = wid & 1;         // 0..1 (16 cols each)
    const int blk = blockIdx.x;

    // --- Load this block's W slice into SMEM (once) ---
    {
        const __half* wsrc = g_whf + (size_t)blk * 32;
#pragma unroll
        for (int i = 0; i < 8; i++) {
            int c = tid + i * 512;          // 0..4095 16B-chunks
            int row = c >> 2, q = c & 3;
            *(uint4*)&ws[row * WS_STR + q * 8] =
                *(const uint4*)&wsrc[(size_t)row * FH + q * 8];
        }
    }
    __syncthreads();

    // ldmatrix lane addressing
    const int lr = lane & 7;
    const int lg = lane >> 3;
    const int a_row_off = ((lg & 1) << 3) + lr;   // row within 16
    const int a_k_off = (lg >> 1) << 3;           // 0 or 8
    const int bt_row = lr + ((lg & 1) << 3);      // k row within 16
    const int bt_c8 = (lane >> 4) << 3;           // 0 or 8 (col half)

    // epilogue mapping: 1 output per thread
    const int e_n = tid >> 3;
    const int e_j = tid & 7;
    const int J0 = blk * 8;
    float creg = 0.0f;

    for (int t = 0; t < TT; t++) {
        const int par = t & 1;
        const __half* __restrict__ hf = g_hf[par];

        // Early xz prefetch (DRAM latency hidden behind the slab loop)
        const float* xr = g_xz + (size_t)(t * NB + e_n) * FH + J0 + e_j;
        float x0 = __ldg(xr);
        float x1 = __ldg(xr + 1024);
        float x2 = __ldg(xr + 2048);
        float x3 = __ldg(xr + 3072);

        float d[2][4];
#pragma unroll
        for (int ct = 0; ct < 2; ct++)
#pragma unroll
            for (int r = 0; r < 4; r++) d[ct][r] = 0.0f;

        // Issue ALL 4 slab loads up front (one commit group each)
#pragma unroll
        for (int s = 0; s < 4; s++) {
            const int hk = s * KSLAB;
            __half* dst = hsm + s * 64 * HS_STR;
#pragma unroll
            for (int i = 0; i < 4; i++) {
                int idx = tid + i * 512;    // 2048 chunks of 16B
                int n = idx >> 5, ch = idx & 31;
                cp16(&dst[n * HS_STR + ch * 8], &hf[n * HH + hk + ch * 8]);
            }
            asm volatile("cp.async.commit_group;");
        }

        // Compute slab s after its group lands (wait_group 3-s pending)
#define REC_SLAB(s, wcnt)                                                          \
        {                                                                          \
            asm volatile("cp.async.wait_group %0;" :: "n"(wcnt));                  \
            __syncthreads();                                                       \
            const __half* hbuf = hsm + (s) * 64 * HS_STR;                          \
            const int kw = (s) * KSLAB;                                            \
            _Pragma("unroll")                                                      \
            for (int ks = 0; ks < 8; ks++) {                                       \
                const int kk0 = warp_k * 128 + ks * 16;                            \
                unsigned a0, a1, a2, a3;                                           \
                unsigned aaddr = s2u(&hbuf[(warp_m * 16 + a_row_off) * HS_STR      \
                                           + kk0 + a_k_off]);                      \
                LDSM_X4(a0, a1, a2, a3, aaddr);                                    \
                unsigned bf0, bf1, bf2, bf3;                                       \
                unsigned baddr = s2u(&ws[(kw + kk0 + bt_row) * WS_STR              \
                                         + warp_c * 16 + bt_c8]);                  \
                LDSM_X4T(bf0, bf1, bf2, bf3, baddr);                               \
                MMA16816F16(d[0][0], d[0][1], d[0][2], d[0][3],                    \
                            a0, a1, a2, a3, bf0, bf1);                             \
                MMA16816F16(d[1][0], d[1][1], d[1][2], d[1][3],                    \
                            a0, a1, a2, a3, bf2, bf3);                             \
            }                                                                      \
        }

        REC_SLAB(0, 3)
        REC_SLAB(1, 2)
        REC_SLAB(2, 1)
        REC_SLAB(3, 0)
#undef REC_SLAB

        __syncthreads();   // all compute done; zbuf (alias of stages 0-1) now safe

        // Scatter partials: zbuf[warp_k][n][c]; warp tile = 16 rows x 16 cols
        {
            const int r4 = lane >> 2;
            const int c2 = (lane & 3) * 2;
            const int nb = warp_m * 16 + r4;
#pragma unroll
            for (int ct = 0; ct < 2; ct++) {
                const int c = warp_c * 16 + ct * 8 + c2;
                zbuf[(warp_k * 64 + nb) * 33 + c] = d[ct][0];
                zbuf[(warp_k * 64 + nb) * 33 + c + 1] = d[ct][1];
                zbuf[(warp_k * 64 + nb + 8) * 33 + c] = d[ct][2];
                zbuf[(warp_k * 64 + nb + 8) * 33 + c + 1] = d[ct][3];
            }
        }
        __syncthreads();

        // Gate epilogue: 1 fixed (n, j) output per thread; c in register
        {
            const int n = e_n, col = J0 + e_j;
            float zi = zbuf[n * 33 + e_j +  0] + zbuf[(64 + n) * 33 + e_j +  0] + x0;
            float zf = zbuf[n * 33 + e_j +  8] + zbuf[(64 + n) * 33 + e_j +  8] + x1;
            float zo = zbuf[n * 33 + e_j + 16] + zbuf[(64 + n) * 33 + e_j + 16] + x2;
            float zg = zbuf[n * 33 + e_j + 24] + zbuf[(64 + n) * 33 + e_j + 24] + x3;

            float iv = fsig(zi);
            float fv = fsig(zf);
            float ov = fsig(zo);
            float gv = ftanh(zg);

            float cn = fv * creg + iv * gv;
            creg = cn;
            float hn = ov * ftanh(cn);

            int hidx = n * HH + col;
            g_hf[par ^ 1][hidx] = __float2half_rn(hn);
            out[((size_t)n * TT + t) * HH + col] = hn;
        }

        // Grid-wide barrier v2 (slot arrivals + block-0 aggregation)
        if (t + 1 < TT) {
            const unsigned target = (unsigned)(t + 1);
            __syncthreads();                    // all h writes issued
            if (tid == 0) {
                __threadfence();                // order h writes before arrival
                st_release(&g_arrive[blk], target);
            }
            if (blk == 0) {
                if (tid < 128) spin_until(&g_arrive[tid], target);
                __syncthreads();
                if (tid == 0) st_release(&g_phase, target);
            }
            if (tid == 0) spin_until(&g_phase, target);
            __syncthreads();
        }
    }
}

// ---------------------------------------------------------------------------
// Launcher (graph-capturable: kernel launches only)
// ---------------------------------------------------------------------------
extern "C" void kernel_launch(void* const* d_in, const int* in_sizes, int n_in,
                              void* d_out, int out_size) {
    const float* x  = (const float*)d_in[0];
    const float* h0 = (const float*)d_in[1];
    const float* Wx = (const float*)d_in[2];
    const float* Wh = (const float*)d_in[3];
    const float* b  = (const float*)d_in[4];
    float* out = (float*)d_out;

    static int attr_set = 0;
    if (!attr_set) {
        cudaFuncSetAttribute(lstm_persistent,
                             cudaFuncAttributeMaxDynamicSharedMemorySize, P_SMEM);
        cudaFuncSetAttribute(gemm1_mma,
                             cudaFuncAttributeMaxDynamicSharedMemorySize, G1_SMEM);
        attr_set = 1;
    }

    init_kernel<<<(NB * HH + 255) / 256, 256>>>(h0);
    split_wh_kernel<<<(DD * FH + 255) / 256, 256>>>(Wh);
    split_wx_kernel<<<(DD * FH + 255) / 256, 256>>>(Wx);
    split_x_kernel<<<((size_t)MM * DD + 511) / 512, 512>>>(x);

    dim3 g1(FH / 128, MM / 128);   // (32, 256)
    gemm1_mma<<<g1, 256, G1_SMEM>>>(b);

    lstm_persistent<<<128, 512, P_SMEM>>>(out);
}